// round 9
// baseline (speedup 1.0000x reference)
#include <cuda_runtime.h>
#include <cuda_fp16.h>
#include <stdint.h>

// ---------------- problem constants -----------------------------------------
#define LL 4096
#define BB 4
#define DD 1024
#define HH 16
#define HD 64
#define ROWS (LL*BB)          // 16384
#define BH   (BB*HH)          // 64
#define KV_PARTS 16
#define LPART (LL/KV_PARTS)   // 256

// ---------------- scratch (device globals; cudaMalloc is banned) ------------
__device__ __align__(256) __half g_xh  [(size_t)ROWS*DD];    // X in f16
__device__ __align__(256) __half g_wh  [(size_t)3*DD*DD];    // [Wq;Wk;Wv] f16
__device__ __align__(256) __half g_woph[(size_t)DD*DD];      // Wo permuted f16
__device__ __align__(256) float  g_bqkv[(size_t)3*DD];       // [bq;bk;bv]
__device__ __align__(256) __half g_qh  [(size_t)ROWS*DD];    // q (unscaled) f16
__device__ __align__(256) __half g_kh  [(size_t)ROWS*DD];
__device__ __align__(256) __half g_vh  [(size_t)ROWS*DD];
__device__ __align__(256) __half g_ah  [(size_t)ROWS*DD];    // attn out f16
__device__ __align__(256) float  g_kvp [(size_t)KV_PARTS*BH*HD*HD];
__device__ __align__(256) float  g_kvT [(size_t)BH*HD*HD];

// ---------------- helpers -----------------------------------------------------
__device__ __forceinline__ uint32_t f2tf(float x) {
    uint32_t u; asm("cvt.rna.tf32.f32 %0, %1;" : "=r"(u) : "f"(x)); return u;
}
__device__ __forceinline__ uint32_t smem_u32(const void* p) {
    uint32_t a;
    asm("{ .reg .u64 t; cvta.to.shared.u64 t, %1; cvt.u32.u64 %0, t; }" : "=r"(a) : "l"(p));
    return a;
}
__device__ __forceinline__ void cp16(uint32_t saddr, const void* gaddr) {
    asm volatile("cp.async.cg.shared.global [%0], [%1], 16;" :: "r"(saddr), "l"(gaddr));
}
__device__ __forceinline__ void ldsm4(uint32_t* r, uint32_t a) {
    asm volatile("ldmatrix.sync.aligned.m8n8.x4.shared.b16 {%0,%1,%2,%3}, [%4];"
        : "=r"(r[0]), "=r"(r[1]), "=r"(r[2]), "=r"(r[3]) : "r"(a));
}
__device__ __forceinline__ void mma16(float c[4], const uint32_t a[4],
                                      uint32_t b0, uint32_t b1) {
    asm volatile(
        "mma.sync.aligned.m16n8k16.row.col.f32.f16.f16.f32 "
        "{%0,%1,%2,%3}, {%4,%5,%6,%7}, {%8,%9}, {%0,%1,%2,%3};"
        : "+f"(c[0]), "+f"(c[1]), "+f"(c[2]), "+f"(c[3])
        : "r"(a[0]), "r"(a[1]), "r"(a[2]), "r"(a[3]), "r"(b0), "r"(b1));
}
__device__ __forceinline__ void mma8(float c[4], const uint32_t a[4],
                                     uint32_t b0, uint32_t b1) {
    asm volatile(
        "mma.sync.aligned.m16n8k8.row.col.f32.tf32.tf32.f32 "
        "{%0,%1,%2,%3}, {%4,%5,%6,%7}, {%8,%9}, {%0,%1,%2,%3};"
        : "+f"(c[0]), "+f"(c[1]), "+f"(c[2]), "+f"(c[3])
        : "r"(a[0]), "r"(a[1]), "r"(a[2]), "r"(a[3]), "r"(b0), "r"(b1));
}

// =============================================================================
// Fused prep kernel: block-range dispatch
//   [0, 16384)            x -> f16
//   [16384, 19456)        pack Wq/Wk/Wv -> f16
//   [19456, 20480)        Wo permute -> f16
//   [20480, 20492)        pack biases
// =============================================================================
__global__ void prep_all(const float* __restrict__ X,
                         const float* __restrict__ Wq, const float* __restrict__ Wk,
                         const float* __restrict__ Wv,
                         const float* __restrict__ bq, const float* __restrict__ bk,
                         const float* __restrict__ bv,
                         const float* __restrict__ Wo) {
    const int blk = blockIdx.x;
    const int tid = threadIdx.x;
    if (blk < 16384) {
        size_t i = ((size_t)blk * 256 + tid) * 4;
        float4 v = *(const float4*)(X + i);
        *(__half2*)(g_xh + i)     = __floats2half2_rn(v.x, v.y);
        *(__half2*)(g_xh + i + 2) = __floats2half2_rn(v.z, v.w);
    } else if (blk < 19456) {
        int r = blk - 16384;                            // 0..3071
        const float* src = (r < 1024) ? Wq : (r < 2048) ? Wk : Wv;
        int lr = r & 1023;
        int c = tid * 4;
        float4 v = *(const float4*)(src + (size_t)lr * DD + c);
        *(__half2*)(g_wh + (size_t)r * DD + c)     = __floats2half2_rn(v.x, v.y);
        *(__half2*)(g_wh + (size_t)r * DD + c + 2) = __floats2half2_rn(v.z, v.w);
    } else if (blk < 20480) {
        __shared__ float srow[DD];
        const int j = blk - 19456;
#pragma unroll
        for (int i = 0; i < 4; ++i) srow[tid + 256*i] = Wo[(size_t)j*DD + tid + 256*i];
        __syncthreads();
#pragma unroll
        for (int i = 0; i < 4; ++i) {
            int f = tid + 256*i;                         // f = h*64 + t
            g_woph[(size_t)j*DD + f] = __float2half_rn(srow[((f & 63) << 4) | (f >> 6)]);
        }
    } else {
        int idx = (blk - 20480) * 256 + tid;             // 0..3071
        int t = idx >> 10;
        const float* src = (t == 0) ? bq : (t == 1) ? bk : bv;
        g_bqkv[idx] = src[idx & 1023];
    }
}

// =============================================================================
// FP16 tensor-core GEMM:  C = A @ B^T + bias
//   block 128x128, BK=64, 4 warps, warp tile 64x64, 3-stage cp.async pipeline,
//   ldmatrix.x4, XOR-8 swizzled 128B smem rows, strength-reduced addressing
//   (all smem/gmem offsets are base + immediate), single barrier per K-chunk.
//   2 CTAs/SM.
// =============================================================================
#define STA  16384                 // A stage bytes (128 rows x 128B)
#define STS_ (2*STA)               // 32768
#define GSMEM (3 * STS_)           // 98304
#define NKT  16                    // 1024 / 64

__global__ void __launch_bounds__(128, 2) gemm_h(
    const __half* __restrict__ A, const __half* __restrict__ B,
    const float* __restrict__ bias,
    void* __restrict__ o0, void* __restrict__ o1, void* __restrict__ o2,
    int half_out)
{
    extern __shared__ char smem[];
    const uint32_t sb = smem_u32(smem);
    const int tid  = threadIdx.x;
    const int wid  = tid >> 5;
    const int lane = tid & 31;
    const int n0 = blockIdx.x * 128;
    const int m0 = blockIdx.y * 128;
    const int wm = (wid & 1) * 64;
    const int wn = (wid >> 1) * 64;

    // ---- cp.async addressing: one base, immediate strides ----
    // thread covers rows {row0 + 16*i}, i=0..7; seg and (row&7) invariant of i
    const int row0 = tid >> 3, seg = tid & 7;
    const uint32_t sm_base = (uint32_t)(row0*128 + ((seg ^ (row0 & 7)) << 4));
    const char* Abase = (const char*)A + (size_t)m0 * 2048 + row0*2048 + seg*16;
    const char* Bbase = (const char*)B + (size_t)n0 * 2048 + row0*2048 + seg*16;

#define LOADC(c) do {                                                    \
        uint32_t ab_ = sb + ((c) % 3)*STS_ + sm_base;                    \
        uint32_t bb_ = ab_ + STA;                                        \
        const char* ga_ = Abase + (size_t)(c)*128;                       \
        const char* gb_ = Bbase + (size_t)(c)*128;                       \
        _Pragma("unroll") for (int i_ = 0; i_ < 8; ++i_) {               \
            cp16(ab_ + i_*2048, ga_ + i_*32768);                         \
            cp16(bb_ + i_*2048, gb_ + i_*32768);                         \
        }                                                                \
        asm volatile("cp.async.commit_group;" ::: "memory");             \
    } while (0)

    // ---- fragment addressing invariants (r&7 == lane&7 for both A and B) ----
    const int a_row = wm + (lane & 15);
    const int b_row = wn + (lane & 7) + ((lane >> 4) << 3);
    const int lo4   = (lane & 7) << 4;
    const int a_hi  = lane >> 4;          // 0/1
    const int b_hi  = (lane >> 3) & 1;    // 0/1

    float acc[4][8][4];
#pragma unroll
    for (int i = 0; i < 4; ++i)
#pragma unroll
        for (int j = 0; j < 8; ++j)
#pragma unroll
            for (int t = 0; t < 4; ++t) acc[i][j][t] = 0.f;

    LOADC(0);
    LOADC(1);

    for (int kt = 0; kt < NKT; ++kt) {
        if (kt + 1 < NKT) asm volatile("cp.async.wait_group 1;" ::: "memory");
        else              asm volatile("cp.async.wait_group 0;" ::: "memory");
        __syncthreads();          // single barrier per K-chunk (3-stage proof)
        if (kt + 2 < NKT) LOADC(kt + 2);

        const uint32_t sa = sb + (kt % 3) * STS_;
        const uint32_t aB = sa + a_row*128;
        const uint32_t bB = sa + STA + b_row*128;

#pragma unroll
        for (int s = 0; s < 4; ++s) {          // four k16 steps within BK=64
            uint32_t af[4][4], bf[4][4];
            const uint32_t asg = (uint32_t)(((2*s + a_hi) << 4) ^ lo4);
            const uint32_t bsg = (uint32_t)(((2*s + b_hi) << 4) ^ lo4);
#pragma unroll
            for (int mt = 0; mt < 4; ++mt)
                ldsm4(af[mt], aB + mt*2048 + asg);
#pragma unroll
            for (int p = 0; p < 4; ++p)
                ldsm4(bf[p], bB + p*2048 + bsg);
#pragma unroll
            for (int mt = 0; mt < 4; ++mt)
#pragma unroll
                for (int nt = 0; nt < 8; ++nt)
                    mma16(acc[mt][nt], af[mt],
                          bf[nt >> 1][(nt & 1) * 2], bf[nt >> 1][(nt & 1) * 2 + 1]);
        }
    }

    // epilogue
    if (half_out) {
        const int t = n0 >> 10;
        __half* outp = (t == 0) ? (__half*)o0 : (t == 1) ? (__half*)o1 : (__half*)o2;
#pragma unroll
        for (int mt = 0; mt < 4; ++mt) {
#pragma unroll
            for (int nt = 0; nt < 8; ++nt) {
                int row = m0 + wm + mt*16 + (lane >> 2);
                int gn  = n0 + wn + nt*8 + 2*(lane & 3);
                int col = gn & 1023;
                float b0 = bias[gn], b1 = bias[gn + 1];
                *(__half2*)&outp[(size_t)row * 1024 + col] =
                    __floats2half2_rn(acc[mt][nt][0] + b0, acc[mt][nt][1] + b1);
                *(__half2*)&outp[(size_t)(row + 8) * 1024 + col] =
                    __floats2half2_rn(acc[mt][nt][2] + b0, acc[mt][nt][3] + b1);
            }
        }
    } else {
        float* outp = (float*)o0;
#pragma unroll
        for (int mt = 0; mt < 4; ++mt) {
#pragma unroll
            for (int nt = 0; nt < 8; ++nt) {
                int row = m0 + wm + mt*16 + (lane >> 2);
                int gn  = n0 + wn + nt*8 + 2*(lane & 3);
                float b0 = bias[gn], b1 = bias[gn + 1];
                *(float2*)&outp[(size_t)row * 1024 + gn] =
                    make_float2(acc[mt][nt][0] + b0, acc[mt][nt][1] + b1);
                *(float2*)&outp[(size_t)(row + 8) * 1024 + gn] =
                    make_float2(acc[mt][nt][2] + b0, acc[mt][nt][3] + b1);
            }
        }
    }
}

// =============================================================================
// partial KV^T per (b,h): kvT[e][d] = sum_l v[l][e]*k[l][d]
// f16 inputs -> tf32 smem staging -> tf32 register mma (fp32 accumulate)
// =============================================================================
#define SW(r, c) (((r) << 5) + ((c) ^ (((((r) + ((r) >> 3)) & 7)) << 2)))

__global__ void __launch_bounds__(256) kv_partial()
{
    const int bh = blockIdx.x, part = blockIdx.y;
    const int b = bh >> 4, h = bh & 15;

    __shared__ uint32_t vTs[64 * 32];
    __shared__ uint32_t kTs[64 * 32];

    const int tid  = threadIdx.x;
    const int lane = tid & 31;
    const int warp = tid >> 5;
    const int wm = (warp >> 1) * 16;
    const int wn = (warp & 1) * 32;

    float acc[4][4];
#pragma unroll
    for (int i = 0; i < 4; ++i)
#pragma unroll
        for (int t = 0; t < 4; ++t) acc[i][t] = 0.f;

    const int l_lo = tid >> 3;
    const int d8   = (tid & 7) * 8;
    const size_t colbase = (size_t)h * 64;

    for (int l0 = part * LPART; l0 < part * LPART + LPART; l0 += 32) {
        size_t g = ((size_t)(l0 + l_lo) * BB + b) * DD + colbase + d8;
        uint4 rv = *(const uint4*)(g_vh + g);     // 8 halves
        uint4 rk = *(const uint4*)(g_kh + g);
        const __half2* hv = (const __half2*)&rv;
        const __half2* hk = (const __half2*)&rk;
#pragma unroll
        for (int j = 0; j < 4; ++j) {
            float2 fv = __half22float2(hv[j]);
            float2 fk = __half22float2(hk[j]);
            vTs[SW(d8 + 2*j,     l_lo)] = f2tf(fv.x);
            vTs[SW(d8 + 2*j + 1, l_lo)] = f2tf(fv.y);
            kTs[SW(d8 + 2*j,     l_lo)] = f2tf(fk.x);
            kTs[SW(d8 + 2*j + 1, l_lo)] = f2tf(fk.y);
        }
        __syncthreads();

#pragma unroll
        for (int kk = 0; kk < 32; kk += 8) {
            uint32_t af[4];
            int r = wm + (lane >> 2);
            int c = kk + (lane & 3);
            af[0] = vTs[SW(r,     c)];
            af[1] = vTs[SW(r + 8, c)];
            af[2] = vTs[SW(r,     c + 4)];
            af[3] = vTs[SW(r + 8, c + 4)];
#pragma unroll
            for (int nt = 0; nt < 4; ++nt) {
                int rn = wn + nt*8 + (lane >> 2);
                uint32_t b0 = kTs[SW(rn, c)];
                uint32_t b1 = kTs[SW(rn, c + 4)];
                mma8(acc[nt], af, b0, b1);
            }
        }
        __syncthreads();
    }

    float* out = g_kvp + ((size_t)part * BH + bh) * 4096;
#pragma unroll
    for (int nt = 0; nt < 4; ++nt) {
        int e = wm + (lane >> 2);
        int d = wn + nt*8 + 2*(lane & 3);
        *(float2*)&out[(e    ) * 64 + d] = make_float2(acc[nt][0], acc[nt][1]);
        *(float2*)&out[(e + 8) * 64 + d] = make_float2(acc[nt][2], acc[nt][3]);
    }
}

__global__ void kv_reduce() {
    const int bh = blockIdx.x;
    const int tid = threadIdx.x;
#pragma unroll
    for (int j = 0; j < 16; ++j) {
        int i = tid + 256 * j;
        float s = 0.f;
#pragma unroll
        for (int p = 0; p < KV_PARTS; ++p)
            s += g_kvp[((size_t)p * BH + bh) * 4096 + i];
        g_kvT[(size_t)bh * 4096 + i] = s;
    }
}

// =============================================================================
// attn = (q @ kvT^T) * (0.125/scalar) per (b,h); f16 in (q), f16 out
// =============================================================================
__global__ void __launch_bounds__(128) attn_qkv(const float* __restrict__ scalar_ptr)
{
    const int lc = blockIdx.x;
    const int h  = blockIdx.y;
    const int b  = blockIdx.z;
    const int bh = b * 16 + h;
    const int l0 = lc * 64;

    __shared__ uint32_t qs [64][68];
    __shared__ uint32_t kvs[64][68];

    const int tid  = threadIdx.x;
    const int lane = tid & 31;
    const int warp = tid >> 5;
    const int wm   = warp * 16;

#pragma unroll
    for (int i = 0; i < 8; ++i) {
        int s   = tid + 128 * i;
        int row = s >> 4;
        int c4  = (s & 15) * 4;
        uint2 rq = *(const uint2*)(g_qh + ((size_t)(l0 + row) * BB + b) * DD
                                        + (size_t)h * 64 + c4);   // 4 halves
        const __half2* hq = (const __half2*)&rq;
        float2 q0 = __half22float2(hq[0]);
        float2 q1 = __half22float2(hq[1]);
        float4 fk = *(const float4*)(g_kvT + (size_t)bh * 4096 + row * 64 + c4);
        uint4 tq = { f2tf(q0.x), f2tf(q0.y), f2tf(q1.x), f2tf(q1.y) };
        uint4 tk = { f2tf(fk.x), f2tf(fk.y), f2tf(fk.z), f2tf(fk.w) };
        *(uint4*)&qs [row][c4] = tq;
        *(uint4*)&kvs[row][c4] = tk;
    }
    __syncthreads();

    float acc[8][4];
#pragma unroll
    for (int i = 0; i < 8; ++i)
#pragma unroll
        for (int t = 0; t < 4; ++t) acc[i][t] = 0.f;

#pragma unroll
    for (int kk = 0; kk < 64; kk += 8) {
        uint32_t af[4];
        int r = wm + (lane >> 2);
        int c = kk + (lane & 3);
        af[0] = qs[r    ][c    ];
        af[1] = qs[r + 8][c    ];
        af[2] = qs[r    ][c + 4];
        af[3] = qs[r + 8][c + 4];
#pragma unroll
        for (int nt = 0; nt < 8; ++nt) {
            int rn = nt*8 + (lane >> 2);
            uint32_t b0 = kvs[rn][c];
            uint32_t b1 = kvs[rn][c + 4];
            mma8(acc[nt], af, b0, b1);
        }
    }

    const float scale = 0.125f / (*scalar_ptr);
#pragma unroll
    for (int nt = 0; nt < 8; ++nt) {
        int l = l0 + wm + (lane >> 2);
        int e = nt*8 + 2*(lane & 3);
        size_t o0 = ((size_t)l * BB + b) * DD + (size_t)h * 64 + e;
        size_t o1 = ((size_t)(l + 8) * BB + b) * DD + (size_t)h * 64 + e;
        *(__half2*)&g_ah[o0] = __floats2half2_rn(acc[nt][0]*scale, acc[nt][1]*scale);
        *(__half2*)&g_ah[o1] = __floats2half2_rn(acc[nt][2]*scale, acc[nt][3]*scale);
    }
}

// =============================================================================
// launch
// =============================================================================
extern "C" void kernel_launch(void* const* d_in, const int* in_sizes, int n_in,
                              void* d_out, int out_size) {
    const float* x      = (const float*)d_in[0];
    const float* Wq     = (const float*)d_in[2];
    const float* bq     = (const float*)d_in[3];
    const float* Wk     = (const float*)d_in[4];
    const float* bk     = (const float*)d_in[5];
    const float* Wv     = (const float*)d_in[6];
    const float* bv     = (const float*)d_in[7];
    const float* Wo     = (const float*)d_in[8];
    const float* bo     = (const float*)d_in[9];
    const float* scalar = (const float*)d_in[10];
    float* out = (float*)d_out;

    __half *xh, *wh, *woph, *ah, *qh, *kh, *vh;
    float *bqkv;
    cudaGetSymbolAddress((void**)&xh,   g_xh);
    cudaGetSymbolAddress((void**)&wh,   g_wh);
    cudaGetSymbolAddress((void**)&woph, g_woph);
    cudaGetSymbolAddress((void**)&ah,   g_ah);
    cudaGetSymbolAddress((void**)&qh,   g_qh);
    cudaGetSymbolAddress((void**)&kh,   g_kh);
    cudaGetSymbolAddress((void**)&vh,   g_vh);
    cudaGetSymbolAddress((void**)&bqkv, g_bqkv);

    cudaFuncSetAttribute(gemm_h, cudaFuncAttributeMaxDynamicSharedMemorySize, GSMEM);

    // fused prep: x->f16, pack W, permute Wo, pack biases
    prep_all<<<20492, 256>>>(x, Wq, Wk, Wv, bq, bk, bv, Wo);

    // fused QKV projection: N = 3072, f16 outputs
    gemm_h<<<dim3(3*DD/128, ROWS/128), 128, GSMEM>>>(
        xh, wh, bqkv, qh, kh, vh, 1);

    kv_partial<<<dim3(BH, KV_PARTS), 256>>>();
    kv_reduce<<<BH, 256>>>();
    attn_qkv<<<dim3(LL / 64, HH, BB), 128>>>(scalar);

    // output projection: N = 1024, fp32 output
    gemm_h<<<dim3(DD/128, ROWS/128), 128, GSMEM>>>(
        ah, woph, bo, out, out, out, 0);
}

// round 10
// speedup vs baseline: 1.0198x; 1.0198x over previous
#include <cuda_runtime.h>
#include <cuda_fp16.h>
#include <stdint.h>

// ---------------- problem constants -----------------------------------------
#define LL 4096
#define BB 4
#define DD 1024
#define HH 16
#define HD 64
#define ROWS (LL*BB)          // 16384
#define BH   (BB*HH)          // 64
#define KV_PARTS 16
#define LPART (LL/KV_PARTS)   // 256

// ---------------- scratch (device globals; cudaMalloc is banned) ------------
__device__ __align__(256) __half g_xh  [(size_t)ROWS*DD];    // X in f16
__device__ __align__(256) __half g_wh  [(size_t)3*DD*DD];    // [Wq;Wk;Wv] f16
__device__ __align__(256) __half g_woph[(size_t)DD*DD];      // Wo permuted f16
__device__ __align__(256) float  g_bqkv[(size_t)3*DD];       // [bq;bk;bv]
__device__ __align__(256) __half g_qh  [(size_t)ROWS*DD];    // q (unscaled) f16
__device__ __align__(256) __half g_kh  [(size_t)ROWS*DD];
__device__ __align__(256) __half g_vh  [(size_t)ROWS*DD];
__device__ __align__(256) __half g_ah  [(size_t)ROWS*DD];    // attn out f16
__device__ __align__(256) float  g_kvp [(size_t)KV_PARTS*BH*HD*HD];
__device__ __align__(256) __half g_kvTh[(size_t)BH*HD*HD];   // reduced KV^T, f16

// ---------------- helpers -----------------------------------------------------
__device__ __forceinline__ uint32_t f2tf(float x) {
    uint32_t u; asm("cvt.rna.tf32.f32 %0, %1;" : "=r"(u) : "f"(x)); return u;
}
__device__ __forceinline__ uint32_t smem_u32(const void* p) {
    uint32_t a;
    asm("{ .reg .u64 t; cvta.to.shared.u64 t, %1; cvt.u32.u64 %0, t; }" : "=r"(a) : "l"(p));
    return a;
}
__device__ __forceinline__ void cp16(uint32_t saddr, const void* gaddr) {
    asm volatile("cp.async.cg.shared.global [%0], [%1], 16;" :: "r"(saddr), "l"(gaddr));
}
__device__ __forceinline__ void ldsm4(uint32_t* r, uint32_t a) {
    asm volatile("ldmatrix.sync.aligned.m8n8.x4.shared.b16 {%0,%1,%2,%3}, [%4];"
        : "=r"(r[0]), "=r"(r[1]), "=r"(r[2]), "=r"(r[3]) : "r"(a));
}
__device__ __forceinline__ void mma16(float c[4], const uint32_t a[4],
                                      uint32_t b0, uint32_t b1) {
    asm volatile(
        "mma.sync.aligned.m16n8k16.row.col.f32.f16.f16.f32 "
        "{%0,%1,%2,%3}, {%4,%5,%6,%7}, {%8,%9}, {%0,%1,%2,%3};"
        : "+f"(c[0]), "+f"(c[1]), "+f"(c[2]), "+f"(c[3])
        : "r"(a[0]), "r"(a[1]), "r"(a[2]), "r"(a[3]), "r"(b0), "r"(b1));
}
__device__ __forceinline__ void mma8(float c[4], const uint32_t a[4],
                                     uint32_t b0, uint32_t b1) {
    asm volatile(
        "mma.sync.aligned.m16n8k8.row.col.f32.tf32.tf32.f32 "
        "{%0,%1,%2,%3}, {%4,%5,%6,%7}, {%8,%9}, {%0,%1,%2,%3};"
        : "+f"(c[0]), "+f"(c[1]), "+f"(c[2]), "+f"(c[3])
        : "r"(a[0]), "r"(a[1]), "r"(a[2]), "r"(a[3]), "r"(b0), "r"(b1));
}

// =============================================================================
// Fused prep kernel: block-range dispatch
// =============================================================================
__global__ void prep_all(const float* __restrict__ X,
                         const float* __restrict__ Wq, const float* __restrict__ Wk,
                         const float* __restrict__ Wv,
                         const float* __restrict__ bq, const float* __restrict__ bk,
                         const float* __restrict__ bv,
                         const float* __restrict__ Wo) {
    const int blk = blockIdx.x;
    const int tid = threadIdx.x;
    if (blk < 16384) {
        size_t i = ((size_t)blk * 256 + tid) * 4;
        float4 v = *(const float4*)(X + i);
        *(__half2*)(g_xh + i)     = __floats2half2_rn(v.x, v.y);
        *(__half2*)(g_xh + i + 2) = __floats2half2_rn(v.z, v.w);
    } else if (blk < 19456) {
        int r = blk - 16384;                            // 0..3071
        const float* src = (r < 1024) ? Wq : (r < 2048) ? Wk : Wv;
        int lr = r & 1023;
        int c = tid * 4;
        float4 v = *(const float4*)(src + (size_t)lr * DD + c);
        *(__half2*)(g_wh + (size_t)r * DD + c)     = __floats2half2_rn(v.x, v.y);
        *(__half2*)(g_wh + (size_t)r * DD + c + 2) = __floats2half2_rn(v.z, v.w);
    } else if (blk < 20480) {
        __shared__ float srow[DD];
        const int j = blk - 19456;
#pragma unroll
        for (int i = 0; i < 4; ++i) srow[tid + 256*i] = Wo[(size_t)j*DD + tid + 256*i];
        __syncthreads();
#pragma unroll
        for (int i = 0; i < 4; ++i) {
            int f = tid + 256*i;                         // f = h*64 + t
            g_woph[(size_t)j*DD + f] = __float2half_rn(srow[((f & 63) << 4) | (f >> 6)]);
        }
    } else {
        int idx = (blk - 20480) * 256 + tid;             // 0..3071
        int t = idx >> 10;
        const float* src = (t == 0) ? bq : (t == 1) ? bk : bv;
        g_bqkv[idx] = src[idx & 1023];
    }
}

// =============================================================================
// FP16 tensor-core GEMM:  C = A @ B^T + bias   (unchanged from R9)
// =============================================================================
#define STA  16384                 // A stage bytes (128 rows x 128B)
#define STS_ (2*STA)               // 32768
#define GSMEM (3 * STS_)           // 98304
#define NKT  16                    // 1024 / 64

__global__ void __launch_bounds__(128, 2) gemm_h(
    const __half* __restrict__ A, const __half* __restrict__ B,
    const float* __restrict__ bias,
    void* __restrict__ o0, void* __restrict__ o1, void* __restrict__ o2,
    int half_out)
{
    extern __shared__ char smem[];
    const uint32_t sb = smem_u32(smem);
    const int tid  = threadIdx.x;
    const int wid  = tid >> 5;
    const int lane = tid & 31;
    const int n0 = blockIdx.x * 128;
    const int m0 = blockIdx.y * 128;
    const int wm = (wid & 1) * 64;
    const int wn = (wid >> 1) * 64;

    const int row0 = tid >> 3, seg = tid & 7;
    const uint32_t sm_base = (uint32_t)(row0*128 + ((seg ^ (row0 & 7)) << 4));
    const char* Abase = (const char*)A + (size_t)m0 * 2048 + row0*2048 + seg*16;
    const char* Bbase = (const char*)B + (size_t)n0 * 2048 + row0*2048 + seg*16;

#define LOADC(c) do {                                                    \
        uint32_t ab_ = sb + ((c) % 3)*STS_ + sm_base;                    \
        uint32_t bb_ = ab_ + STA;                                        \
        const char* ga_ = Abase + (size_t)(c)*128;                       \
        const char* gb_ = Bbase + (size_t)(c)*128;                       \
        _Pragma("unroll") for (int i_ = 0; i_ < 8; ++i_) {               \
            cp16(ab_ + i_*2048, ga_ + i_*32768);                         \
            cp16(bb_ + i_*2048, gb_ + i_*32768);                         \
        }                                                                \
        asm volatile("cp.async.commit_group;" ::: "memory");             \
    } while (0)

    const int a_row = wm + (lane & 15);
    const int b_row = wn + (lane & 7) + ((lane >> 4) << 3);
    const int lo4   = (lane & 7) << 4;
    const int a_hi  = lane >> 4;
    const int b_hi  = (lane >> 3) & 1;

    float acc[4][8][4];
#pragma unroll
    for (int i = 0; i < 4; ++i)
#pragma unroll
        for (int j = 0; j < 8; ++j)
#pragma unroll
            for (int t = 0; t < 4; ++t) acc[i][j][t] = 0.f;

    LOADC(0);
    LOADC(1);

    for (int kt = 0; kt < NKT; ++kt) {
        if (kt + 1 < NKT) asm volatile("cp.async.wait_group 1;" ::: "memory");
        else              asm volatile("cp.async.wait_group 0;" ::: "memory");
        __syncthreads();
        if (kt + 2 < NKT) LOADC(kt + 2);

        const uint32_t sa = sb + (kt % 3) * STS_;
        const uint32_t aB = sa + a_row*128;
        const uint32_t bB = sa + STA + b_row*128;

#pragma unroll
        for (int s = 0; s < 4; ++s) {
            uint32_t af[4][4], bf[4][4];
            const uint32_t asg = (uint32_t)(((2*s + a_hi) << 4) ^ lo4);
            const uint32_t bsg = (uint32_t)(((2*s + b_hi) << 4) ^ lo4);
#pragma unroll
            for (int mt = 0; mt < 4; ++mt)
                ldsm4(af[mt], aB + mt*2048 + asg);
#pragma unroll
            for (int p = 0; p < 4; ++p)
                ldsm4(bf[p], bB + p*2048 + bsg);
#pragma unroll
            for (int mt = 0; mt < 4; ++mt)
#pragma unroll
                for (int nt = 0; nt < 8; ++nt)
                    mma16(acc[mt][nt], af[mt],
                          bf[nt >> 1][(nt & 1) * 2], bf[nt >> 1][(nt & 1) * 2 + 1]);
        }
    }

    if (half_out) {
        const int t = n0 >> 10;
        __half* outp = (t == 0) ? (__half*)o0 : (t == 1) ? (__half*)o1 : (__half*)o2;
#pragma unroll
        for (int mt = 0; mt < 4; ++mt) {
#pragma unroll
            for (int nt = 0; nt < 8; ++nt) {
                int row = m0 + wm + mt*16 + (lane >> 2);
                int gn  = n0 + wn + nt*8 + 2*(lane & 3);
                int col = gn & 1023;
                float b0 = bias[gn], b1 = bias[gn + 1];
                *(__half2*)&outp[(size_t)row * 1024 + col] =
                    __floats2half2_rn(acc[mt][nt][0] + b0, acc[mt][nt][1] + b1);
                *(__half2*)&outp[(size_t)(row + 8) * 1024 + col] =
                    __floats2half2_rn(acc[mt][nt][2] + b0, acc[mt][nt][3] + b1);
            }
        }
    } else {
        float* outp = (float*)o0;
#pragma unroll
        for (int mt = 0; mt < 4; ++mt) {
#pragma unroll
            for (int nt = 0; nt < 8; ++nt) {
                int row = m0 + wm + mt*16 + (lane >> 2);
                int gn  = n0 + wn + nt*8 + 2*(lane & 3);
                float b0 = bias[gn], b1 = bias[gn + 1];
                *(float2*)&outp[(size_t)row * 1024 + gn] =
                    make_float2(acc[mt][nt][0] + b0, acc[mt][nt][1] + b1);
                *(float2*)&outp[(size_t)(row + 8) * 1024 + gn] =
                    make_float2(acc[mt][nt][2] + b0, acc[mt][nt][3] + b1);
            }
        }
    }
}

// =============================================================================
// partial KV^T per (b,h): kvT[e][d] = sum_l v[l][e]*k[l][d]
// =============================================================================
#define SW(r, c) (((r) << 5) + ((c) ^ (((((r) + ((r) >> 3)) & 7)) << 2)))

__global__ void __launch_bounds__(256) kv_partial()
{
    const int bh = blockIdx.x, part = blockIdx.y;
    const int b = bh >> 4, h = bh & 15;

    __shared__ uint32_t vTs[64 * 32];
    __shared__ uint32_t kTs[64 * 32];

    const int tid  = threadIdx.x;
    const int lane = tid & 31;
    const int warp = tid >> 5;
    const int wm = (warp >> 1) * 16;
    const int wn = (warp & 1) * 32;

    float acc[4][4];
#pragma unroll
    for (int i = 0; i < 4; ++i)
#pragma unroll
        for (int t = 0; t < 4; ++t) acc[i][t] = 0.f;

    const int l_lo = tid >> 3;
    const int d8   = (tid & 7) * 8;
    const size_t colbase = (size_t)h * 64;

    for (int l0 = part * LPART; l0 < part * LPART + LPART; l0 += 32) {
        size_t g = ((size_t)(l0 + l_lo) * BB + b) * DD + colbase + d8;
        uint4 rv = *(const uint4*)(g_vh + g);     // 8 halves
        uint4 rk = *(const uint4*)(g_kh + g);
        const __half2* hv = (const __half2*)&rv;
        const __half2* hk = (const __half2*)&rk;
#pragma unroll
        for (int j = 0; j < 4; ++j) {
            float2 fv = __half22float2(hv[j]);
            float2 fk = __half22float2(hk[j]);
            vTs[SW(d8 + 2*j,     l_lo)] = f2tf(fv.x);
            vTs[SW(d8 + 2*j + 1, l_lo)] = f2tf(fv.y);
            kTs[SW(d8 + 2*j,     l_lo)] = f2tf(fk.x);
            kTs[SW(d8 + 2*j + 1, l_lo)] = f2tf(fk.y);
        }
        __syncthreads();

#pragma unroll
        for (int kk = 0; kk < 32; kk += 8) {
            uint32_t af[4];
            int r = wm + (lane >> 2);
            int c = kk + (lane & 3);
            af[0] = vTs[SW(r,     c)];
            af[1] = vTs[SW(r + 8, c)];
            af[2] = vTs[SW(r,     c + 4)];
            af[3] = vTs[SW(r + 8, c + 4)];
#pragma unroll
            for (int nt = 0; nt < 4; ++nt) {
                int rn = wn + nt*8 + (lane >> 2);
                uint32_t b0 = kTs[SW(rn, c)];
                uint32_t b1 = kTs[SW(rn, c + 4)];
                mma8(acc[nt], af, b0, b1);
            }
        }
        __syncthreads();
    }

    float* out = g_kvp + ((size_t)part * BH + bh) * 4096;
#pragma unroll
    for (int nt = 0; nt < 4; ++nt) {
        int e = wm + (lane >> 2);
        int d = wn + nt*8 + 2*(lane & 3);
        *(float2*)&out[(e    ) * 64 + d] = make_float2(acc[nt][0], acc[nt][1]);
        *(float2*)&out[(e + 8) * 64 + d] = make_float2(acc[nt][2], acc[nt][3]);
    }
}

// deterministic fixed-order reduce; grid (BH, 16); output f16
__global__ void kv_reduce() {
    const int bh = blockIdx.x;
    const int i  = blockIdx.y * 256 + threadIdx.x;      // 0..4095
    float s = 0.f;
#pragma unroll
    for (int p = 0; p < KV_PARTS; ++p)
        s += g_kvp[((size_t)p * BH + bh) * 4096 + i];
    g_kvTh[(size_t)bh * 4096 + i] = __float2half_rn(s);
}

// =============================================================================
// attn = (q @ kvT^T) * (0.125/scalar) per (b,h); f16 in (q, kvT), f16 out
// =============================================================================
__global__ void __launch_bounds__(128) attn_qkv(const float* __restrict__ scalar_ptr)
{
    const int lc = blockIdx.x;
    const int h  = blockIdx.y;
    const int b  = blockIdx.z;
    const int bh = b * 16 + h;
    const int l0 = lc * 64;

    __shared__ uint32_t qs [64][68];
    __shared__ uint32_t kvs[64][68];

    const int tid  = threadIdx.x;
    const int lane = tid & 31;
    const int warp = tid >> 5;
    const int wm   = warp * 16;

#pragma unroll
    for (int i = 0; i < 8; ++i) {
        int s   = tid + 128 * i;
        int row = s >> 4;
        int c4  = (s & 15) * 4;
        uint2 rq = *(const uint2*)(g_qh + ((size_t)(l0 + row) * BB + b) * DD
                                        + (size_t)h * 64 + c4);   // 4 halves
        uint2 rk = *(const uint2*)(g_kvTh + (size_t)bh * 4096 + row * 64 + c4);
        const __half2* hq = (const __half2*)&rq;
        const __half2* hk = (const __half2*)&rk;
        float2 q0 = __half22float2(hq[0]);
        float2 q1 = __half22float2(hq[1]);
        float2 k0 = __half22float2(hk[0]);
        float2 k1 = __half22float2(hk[1]);
        uint4 tq = { f2tf(q0.x), f2tf(q0.y), f2tf(q1.x), f2tf(q1.y) };
        uint4 tk = { f2tf(k0.x), f2tf(k0.y), f2tf(k1.x), f2tf(k1.y) };
        *(uint4*)&qs [row][c4] = tq;
        *(uint4*)&kvs[row][c4] = tk;
    }
    __syncthreads();

    float acc[8][4];
#pragma unroll
    for (int i = 0; i < 8; ++i)
#pragma unroll
        for (int t = 0; t < 4; ++t) acc[i][t] = 0.f;

#pragma unroll
    for (int kk = 0; kk < 64; kk += 8) {
        uint32_t af[4];
        int r = wm + (lane >> 2);
        int c = kk + (lane & 3);
        af[0] = qs[r    ][c    ];
        af[1] = qs[r + 8][c    ];
        af[2] = qs[r    ][c + 4];
        af[3] = qs[r + 8][c + 4];
#pragma unroll
        for (int nt = 0; nt < 8; ++nt) {
            int rn = nt*8 + (lane >> 2);
            uint32_t b0 = kvs[rn][c];
            uint32_t b1 = kvs[rn][c + 4];
            mma8(acc[nt], af, b0, b1);
        }
    }

    const float scale = 0.125f / (*scalar_ptr);
#pragma unroll
    for (int nt = 0; nt < 8; ++nt) {
        int l = l0 + wm + (lane >> 2);
        int e = nt*8 + 2*(lane & 3);
        size_t o0 = ((size_t)l * BB + b) * DD + (size_t)h * 64 + e;
        size_t o1 = ((size_t)(l + 8) * BB + b) * DD + (size_t)h * 64 + e;
        *(__half2*)&g_ah[o0] = __floats2half2_rn(acc[nt][0]*scale, acc[nt][1]*scale);
        *(__half2*)&g_ah[o1] = __floats2half2_rn(acc[nt][2]*scale, acc[nt][3]*scale);
    }
}

// =============================================================================
// launch
// =============================================================================
extern "C" void kernel_launch(void* const* d_in, const int* in_sizes, int n_in,
                              void* d_out, int out_size) {
    const float* x      = (const float*)d_in[0];
    const float* Wq     = (const float*)d_in[2];
    const float* bq     = (const float*)d_in[3];
    const float* Wk     = (const float*)d_in[4];
    const float* bk     = (const float*)d_in[5];
    const float* Wv     = (const float*)d_in[6];
    const float* bv     = (const float*)d_in[7];
    const float* Wo     = (const float*)d_in[8];
    const float* bo     = (const float*)d_in[9];
    const float* scalar = (const float*)d_in[10];
    float* out = (float*)d_out;

    __half *xh, *wh, *woph, *ah, *qh, *kh, *vh;
    float *bqkv;
    cudaGetSymbolAddress((void**)&xh,   g_xh);
    cudaGetSymbolAddress((void**)&wh,   g_wh);
    cudaGetSymbolAddress((void**)&woph, g_woph);
    cudaGetSymbolAddress((void**)&ah,   g_ah);
    cudaGetSymbolAddress((void**)&qh,   g_qh);
    cudaGetSymbolAddress((void**)&kh,   g_kh);
    cudaGetSymbolAddress((void**)&vh,   g_vh);
    cudaGetSymbolAddress((void**)&bqkv, g_bqkv);

    cudaFuncSetAttribute(gemm_h, cudaFuncAttributeMaxDynamicSharedMemorySize, GSMEM);

    // fused prep: x->f16, pack W, permute Wo, pack biases
    prep_all<<<20492, 256>>>(x, Wq, Wk, Wv, bq, bk, bv, Wo);

    // fused QKV projection: N = 3072, f16 outputs
    gemm_h<<<dim3(3*DD/128, ROWS/128), 128, GSMEM>>>(
        xh, wh, bqkv, qh, kh, vh, 1);

    kv_partial<<<dim3(BH, KV_PARTS), 256>>>();
    kv_reduce<<<dim3(BH, 16), 256>>>();
    attn_qkv<<<dim3(LL / 64, HH, BB), 128>>>(scalar);

    // output projection: N = 1024, fp32 output
    gemm_h<<<dim3(DD/128, ROWS/128), 128, GSMEM>>>(
        ah, woph, bo, out, out, out, 0);
}

// round 11
// speedup vs baseline: 1.0632x; 1.0426x over previous
#include <cuda_runtime.h>
#include <cuda_fp16.h>
#include <stdint.h>

// ---------------- problem constants -----------------------------------------
#define LL 4096
#define BB 4
#define DD 1024
#define HH 16
#define HD 64
#define ROWS (LL*BB)          // 16384
#define BH   (BB*HH)          // 64
#define KV_PARTS 16
#define LPART (LL/KV_PARTS)   // 256

// ---------------- scratch (device globals; cudaMalloc is banned) ------------
__device__ __align__(256) __half g_xh  [(size_t)ROWS*DD];    // X in f16
__device__ __align__(256) __half g_wh  [(size_t)3*DD*DD];    // [Wq;Wk;Wv] f16
__device__ __align__(256) __half g_woph[(size_t)DD*DD];      // Wo permuted f16
__device__ __align__(256) float  g_bqkv[(size_t)3*DD];       // [bq;bk;bv]
__device__ __align__(256) __half g_qh  [(size_t)ROWS*DD];    // q (unscaled) f16
__device__ __align__(256) __half g_kh  [(size_t)ROWS*DD];
__device__ __align__(256) __half g_vh  [(size_t)ROWS*DD];
__device__ __align__(256) __half g_ah  [(size_t)ROWS*DD];    // attn out f16
__device__ __align__(256) float  g_kvp [(size_t)KV_PARTS*BH*HD*HD];
__device__ __align__(256) __half g_kvTh[(size_t)BH*HD*HD];   // reduced KV^T, f16

// ---------------- helpers -----------------------------------------------------
__device__ __forceinline__ uint32_t f2tf(float x) {
    uint32_t u; asm("cvt.rna.tf32.f32 %0, %1;" : "=r"(u) : "f"(x)); return u;
}
__device__ __forceinline__ uint32_t smem_u32(const void* p) {
    uint32_t a;
    asm("{ .reg .u64 t; cvta.to.shared.u64 t, %1; cvt.u32.u64 %0, t; }" : "=r"(a) : "l"(p));
    return a;
}
__device__ __forceinline__ void cp16(uint32_t saddr, const void* gaddr) {
    asm volatile("cp.async.cg.shared.global [%0], [%1], 16;" :: "r"(saddr), "l"(gaddr));
}
__device__ __forceinline__ void ldsm4(uint32_t* r, uint32_t a) {
    asm volatile("ldmatrix.sync.aligned.m8n8.x4.shared.b16 {%0,%1,%2,%3}, [%4];"
        : "=r"(r[0]), "=r"(r[1]), "=r"(r[2]), "=r"(r[3]) : "r"(a));
}
__device__ __forceinline__ void mma16(float c[4], const uint32_t a[4],
                                      uint32_t b0, uint32_t b1) {
    asm volatile(
        "mma.sync.aligned.m16n8k16.row.col.f32.f16.f16.f32 "
        "{%0,%1,%2,%3}, {%4,%5,%6,%7}, {%8,%9}, {%0,%1,%2,%3};"
        : "+f"(c[0]), "+f"(c[1]), "+f"(c[2]), "+f"(c[3])
        : "r"(a[0]), "r"(a[1]), "r"(a[2]), "r"(a[3]), "r"(b0), "r"(b1));
}
__device__ __forceinline__ void mma8(float c[4], const uint32_t a[4],
                                     uint32_t b0, uint32_t b1) {
    asm volatile(
        "mma.sync.aligned.m16n8k8.row.col.f32.tf32.tf32.f32 "
        "{%0,%1,%2,%3}, {%4,%5,%6,%7}, {%8,%9}, {%0,%1,%2,%3};"
        : "+f"(c[0]), "+f"(c[1]), "+f"(c[2]), "+f"(c[3])
        : "r"(a[0]), "r"(a[1]), "r"(a[2]), "r"(a[3]), "r"(b0), "r"(b1));
}

// =============================================================================
// Fused prep kernel: block-range dispatch
// =============================================================================
__global__ void prep_all(const float* __restrict__ X,
                         const float* __restrict__ Wq, const float* __restrict__ Wk,
                         const float* __restrict__ Wv,
                         const float* __restrict__ bq, const float* __restrict__ bk,
                         const float* __restrict__ bv,
                         const float* __restrict__ Wo) {
    const int blk = blockIdx.x;
    const int tid = threadIdx.x;
    if (blk < 16384) {
        size_t i = ((size_t)blk * 256 + tid) * 4;
        float4 v = *(const float4*)(X + i);
        *(__half2*)(g_xh + i)     = __floats2half2_rn(v.x, v.y);
        *(__half2*)(g_xh + i + 2) = __floats2half2_rn(v.z, v.w);
    } else if (blk < 19456) {
        int r = blk - 16384;                            // 0..3071
        const float* src = (r < 1024) ? Wq : (r < 2048) ? Wk : Wv;
        int lr = r & 1023;
        int c = tid * 4;
        float4 v = *(const float4*)(src + (size_t)lr * DD + c);
        *(__half2*)(g_wh + (size_t)r * DD + c)     = __floats2half2_rn(v.x, v.y);
        *(__half2*)(g_wh + (size_t)r * DD + c + 2) = __floats2half2_rn(v.z, v.w);
    } else if (blk < 20480) {
        __shared__ float srow[DD];
        const int j = blk - 19456;
#pragma unroll
        for (int i = 0; i < 4; ++i) srow[tid + 256*i] = Wo[(size_t)j*DD + tid + 256*i];
        __syncthreads();
#pragma unroll
        for (int i = 0; i < 4; ++i) {
            int f = tid + 256*i;                         // f = h*64 + t
            g_woph[(size_t)j*DD + f] = __float2half_rn(srow[((f & 63) << 4) | (f >> 6)]);
        }
    } else {
        int idx = (blk - 20480) * 256 + tid;             // 0..3071
        int t = idx >> 10;
        const float* src = (t == 0) ? bq : (t == 1) ? bk : bv;
        g_bqkv[idx] = src[idx & 1023];
    }
}

// =============================================================================
// FP16 tensor-core GEMM:  C = A @ B^T + bias
//   block 128x128, BK=64, 4 warps, warp tile 64x64, 3-stage cp.async pipeline,
//   ldmatrix.x4, XOR-8 swizzled 128B smem rows.  cp.async issues for stage
//   kt+2 are SPREAD across the four k16 steps (4 per step) so LSU work hides
//   under the mma stream instead of bursting at the chunk head.  2 CTAs/SM.
// =============================================================================
#define STA  16384                 // A stage bytes (128 rows x 128B)
#define STS_ (2*STA)               // 32768
#define GSMEM (3 * STS_)           // 98304
#define NKT  16                    // 1024 / 64

__global__ void __launch_bounds__(128, 2) gemm_h(
    const __half* __restrict__ A, const __half* __restrict__ B,
    const float* __restrict__ bias,
    void* __restrict__ o0, void* __restrict__ o1, void* __restrict__ o2,
    int half_out)
{
    extern __shared__ char smem[];
    const uint32_t sb = smem_u32(smem);
    const int tid  = threadIdx.x;
    const int wid  = tid >> 5;
    const int lane = tid & 31;
    const int n0 = blockIdx.x * 128;
    const int m0 = blockIdx.y * 128;
    const int wm = (wid & 1) * 64;
    const int wn = (wid >> 1) * 64;

    const int row0 = tid >> 3, seg = tid & 7;
    const uint32_t sm_base = (uint32_t)(row0*128 + ((seg ^ (row0 & 7)) << 4));
    const char* Abase = (const char*)A + (size_t)m0 * 2048 + row0*2048 + seg*16;
    const char* Bbase = (const char*)B + (size_t)n0 * 2048 + row0*2048 + seg*16;

// full-burst load (prologue only)
#define LOADC(c) do {                                                    \
        uint32_t ab_ = sb + ((c) % 3)*STS_ + sm_base;                    \
        uint32_t bb_ = ab_ + STA;                                        \
        const char* ga_ = Abase + (size_t)(c)*128;                       \
        const char* gb_ = Bbase + (size_t)(c)*128;                       \
        _Pragma("unroll") for (int i_ = 0; i_ < 8; ++i_) {               \
            cp16(ab_ + i_*2048, ga_ + i_*32768);                         \
            cp16(bb_ + i_*2048, gb_ + i_*32768);                         \
        }                                                                \
        asm volatile("cp.async.commit_group;" ::: "memory");             \
    } while (0)

    const int a_row = wm + (lane & 15);
    const int b_row = wn + (lane & 7) + ((lane >> 4) << 3);
    const int lo4   = (lane & 7) << 4;
    const int a_hi  = lane >> 4;
    const int b_hi  = (lane >> 3) & 1;

    float acc[4][8][4];
#pragma unroll
    for (int i = 0; i < 4; ++i)
#pragma unroll
        for (int j = 0; j < 8; ++j)
#pragma unroll
            for (int t = 0; t < 4; ++t) acc[i][j][t] = 0.f;

    LOADC(0);
    LOADC(1);

    for (int kt = 0; kt < NKT; ++kt) {
        if (kt + 1 < NKT) asm volatile("cp.async.wait_group 1;" ::: "memory");
        else              asm volatile("cp.async.wait_group 0;" ::: "memory");
        __syncthreads();

        const bool do_load = (kt + 2 < NKT);
        // next-stage bases (stage (kt+2)%3 freed by the barrier above)
        const uint32_t nab = sb + ((kt + 2) % 3)*STS_ + sm_base;
        const uint32_t nbb = nab + STA;
        const char* nga = Abase + (size_t)(kt + 2)*128;
        const char* ngb = Bbase + (size_t)(kt + 2)*128;

        const uint32_t sa = sb + (kt % 3) * STS_;
        const uint32_t aB = sa + a_row*128;
        const uint32_t bB = sa + STA + b_row*128;

#pragma unroll
        for (int s = 0; s < 4; ++s) {
            uint32_t af[4][4], bf[4][4];
            const uint32_t asg = (uint32_t)(((2*s + a_hi) << 4) ^ lo4);
            const uint32_t bsg = (uint32_t)(((2*s + b_hi) << 4) ^ lo4);
#pragma unroll
            for (int mt = 0; mt < 4; ++mt)
                ldsm4(af[mt], aB + mt*2048 + asg);
#pragma unroll
            for (int p = 0; p < 4; ++p)
                ldsm4(bf[p], bB + p*2048 + bsg);
            // spread 4 of the 16 next-stage cp.asyncs into this step
            if (do_load) {
                cp16(nab + (2*s  )*2048, nga + (size_t)(2*s  )*32768);
                cp16(nab + (2*s+1)*2048, nga + (size_t)(2*s+1)*32768);
                cp16(nbb + (2*s  )*2048, ngb + (size_t)(2*s  )*32768);
                cp16(nbb + (2*s+1)*2048, ngb + (size_t)(2*s+1)*32768);
            }
#pragma unroll
            for (int mt = 0; mt < 4; ++mt)
#pragma unroll
                for (int nt = 0; nt < 8; ++nt)
                    mma16(acc[mt][nt], af[mt],
                          bf[nt >> 1][(nt & 1) * 2], bf[nt >> 1][(nt & 1) * 2 + 1]);
        }
        if (do_load)
            asm volatile("cp.async.commit_group;" ::: "memory");
    }

    if (half_out) {
        const int t = n0 >> 10;
        __half* outp = (t == 0) ? (__half*)o0 : (t == 1) ? (__half*)o1 : (__half*)o2;
#pragma unroll
        for (int mt = 0; mt < 4; ++mt) {
#pragma unroll
            for (int nt = 0; nt < 8; ++nt) {
                int row = m0 + wm + mt*16 + (lane >> 2);
                int gn  = n0 + wn + nt*8 + 2*(lane & 3);
                int col = gn & 1023;
                float b0 = bias[gn], b1 = bias[gn + 1];
                *(__half2*)&outp[(size_t)row * 1024 + col] =
                    __floats2half2_rn(acc[mt][nt][0] + b0, acc[mt][nt][1] + b1);
                *(__half2*)&outp[(size_t)(row + 8) * 1024 + col] =
                    __floats2half2_rn(acc[mt][nt][2] + b0, acc[mt][nt][3] + b1);
            }
        }
    } else {
        float* outp = (float*)o0;
#pragma unroll
        for (int mt = 0; mt < 4; ++mt) {
#pragma unroll
            for (int nt = 0; nt < 8; ++nt) {
                int row = m0 + wm + mt*16 + (lane >> 2);
                int gn  = n0 + wn + nt*8 + 2*(lane & 3);
                float b0 = bias[gn], b1 = bias[gn + 1];
                *(float2*)&outp[(size_t)row * 1024 + gn] =
                    make_float2(acc[mt][nt][0] + b0, acc[mt][nt][1] + b1);
                *(float2*)&outp[(size_t)(row + 8) * 1024 + gn] =
                    make_float2(acc[mt][nt][2] + b0, acc[mt][nt][3] + b1);
            }
        }
    }
}

// =============================================================================
// partial KV^T per (b,h): kvT[e][d] = sum_l v[l][e]*k[l][d]
// =============================================================================
#define SW(r, c) (((r) << 5) + ((c) ^ (((((r) + ((r) >> 3)) & 7)) << 2)))

__global__ void __launch_bounds__(256) kv_partial()
{
    const int bh = blockIdx.x, part = blockIdx.y;
    const int b = bh >> 4, h = bh & 15;

    __shared__ uint32_t vTs[64 * 32];
    __shared__ uint32_t kTs[64 * 32];

    const int tid  = threadIdx.x;
    const int lane = tid & 31;
    const int warp = tid >> 5;
    const int wm = (warp >> 1) * 16;
    const int wn = (warp & 1) * 32;

    float acc[4][4];
#pragma unroll
    for (int i = 0; i < 4; ++i)
#pragma unroll
        for (int t = 0; t < 4; ++t) acc[i][t] = 0.f;

    const int l_lo = tid >> 3;
    const int d8   = (tid & 7) * 8;
    const size_t colbase = (size_t)h * 64;

    for (int l0 = part * LPART; l0 < part * LPART + LPART; l0 += 32) {
        size_t g = ((size_t)(l0 + l_lo) * BB + b) * DD + colbase + d8;
        uint4 rv = *(const uint4*)(g_vh + g);     // 8 halves
        uint4 rk = *(const uint4*)(g_kh + g);
        const __half2* hv = (const __half2*)&rv;
        const __half2* hk = (const __half2*)&rk;
#pragma unroll
        for (int j = 0; j < 4; ++j) {
            float2 fv = __half22float2(hv[j]);
            float2 fk = __half22float2(hk[j]);
            vTs[SW(d8 + 2*j,     l_lo)] = f2tf(fv.x);
            vTs[SW(d8 + 2*j + 1, l_lo)] = f2tf(fv.y);
            kTs[SW(d8 + 2*j,     l_lo)] = f2tf(fk.x);
            kTs[SW(d8 + 2*j + 1, l_lo)] = f2tf(fk.y);
        }
        __syncthreads();

#pragma unroll
        for (int kk = 0; kk < 32; kk += 8) {
            uint32_t af[4];
            int r = wm + (lane >> 2);
            int c = kk + (lane & 3);
            af[0] = vTs[SW(r,     c)];
            af[1] = vTs[SW(r + 8, c)];
            af[2] = vTs[SW(r,     c + 4)];
            af[3] = vTs[SW(r + 8, c + 4)];
#pragma unroll
            for (int nt = 0; nt < 4; ++nt) {
                int rn = wn + nt*8 + (lane >> 2);
                uint32_t b0 = kTs[SW(rn, c)];
                uint32_t b1 = kTs[SW(rn, c + 4)];
                mma8(acc[nt], af, b0, b1);
            }
        }
        __syncthreads();
    }

    float* out = g_kvp + ((size_t)part * BH + bh) * 4096;
#pragma unroll
    for (int nt = 0; nt < 4; ++nt) {
        int e = wm + (lane >> 2);
        int d = wn + nt*8 + 2*(lane & 3);
        *(float2*)&out[(e    ) * 64 + d] = make_float2(acc[nt][0], acc[nt][1]);
        *(float2*)&out[(e + 8) * 64 + d] = make_float2(acc[nt][2], acc[nt][3]);
    }
}

// deterministic fixed-order reduce; grid (BH, 16); output f16
__global__ void kv_reduce() {
    const int bh = blockIdx.x;
    const int i  = blockIdx.y * 256 + threadIdx.x;      // 0..4095
    float s = 0.f;
#pragma unroll
    for (int p = 0; p < KV_PARTS; ++p)
        s += g_kvp[((size_t)p * BH + bh) * 4096 + i];
    g_kvTh[(size_t)bh * 4096 + i] = __float2half_rn(s);
}

// =============================================================================
// attn = (q @ kvT^T) * (0.125/scalar) per (b,h); f16 in (q, kvT), f16 out
// =============================================================================
__global__ void __launch_bounds__(128) attn_qkv(const float* __restrict__ scalar_ptr)
{
    const int lc = blockIdx.x;
    const int h  = blockIdx.y;
    const int b  = blockIdx.z;
    const int bh = b * 16 + h;
    const int l0 = lc * 64;

    __shared__ uint32_t qs [64][68];
    __shared__ uint32_t kvs[64][68];

    const int tid  = threadIdx.x;
    const int lane = tid & 31;
    const int warp = tid >> 5;
    const int wm   = warp * 16;

#pragma unroll
    for (int i = 0; i < 8; ++i) {
        int s   = tid + 128 * i;
        int row = s >> 4;
        int c4  = (s & 15) * 4;
        uint2 rq = *(const uint2*)(g_qh + ((size_t)(l0 + row) * BB + b) * DD
                                        + (size_t)h * 64 + c4);   // 4 halves
        uint2 rk = *(const uint2*)(g_kvTh + (size_t)bh * 4096 + row * 64 + c4);
        const __half2* hq = (const __half2*)&rq;
        const __half2* hk = (const __half2*)&rk;
        float2 q0 = __half22float2(hq[0]);
        float2 q1 = __half22float2(hq[1]);
        float2 k0 = __half22float2(hk[0]);
        float2 k1 = __half22float2(hk[1]);
        uint4 tq = { f2tf(q0.x), f2tf(q0.y), f2tf(q1.x), f2tf(q1.y) };
        uint4 tk = { f2tf(k0.x), f2tf(k0.y), f2tf(k1.x), f2tf(k1.y) };
        *(uint4*)&qs [row][c4] = tq;
        *(uint4*)&kvs[row][c4] = tk;
    }
    __syncthreads();

    float acc[8][4];
#pragma unroll
    for (int i = 0; i < 8; ++i)
#pragma unroll
        for (int t = 0; t < 4; ++t) acc[i][t] = 0.f;

#pragma unroll
    for (int kk = 0; kk < 64; kk += 8) {
        uint32_t af[4];
        int r = wm + (lane >> 2);
        int c = kk + (lane & 3);
        af[0] = qs[r    ][c    ];
        af[1] = qs[r + 8][c    ];
        af[2] = qs[r    ][c + 4];
        af[3] = qs[r + 8][c + 4];
#pragma unroll
        for (int nt = 0; nt < 8; ++nt) {
            int rn = nt*8 + (lane >> 2);
            uint32_t b0 = kvs[rn][c];
            uint32_t b1 = kvs[rn][c + 4];
            mma8(acc[nt], af, b0, b1);
        }
    }

    const float scale = 0.125f / (*scalar_ptr);
#pragma unroll
    for (int nt = 0; nt < 8; ++nt) {
        int l = l0 + wm + (lane >> 2);
        int e = nt*8 + 2*(lane & 3);
        size_t o0 = ((size_t)l * BB + b) * DD + (size_t)h * 64 + e;
        size_t o1 = ((size_t)(l + 8) * BB + b) * DD + (size_t)h * 64 + e;
        *(__half2*)&g_ah[o0] = __floats2half2_rn(acc[nt][0]*scale, acc[nt][1]*scale);
        *(__half2*)&g_ah[o1] = __floats2half2_rn(acc[nt][2]*scale, acc[nt][3]*scale);
    }
}

// =============================================================================
// launch
// =============================================================================
extern "C" void kernel_launch(void* const* d_in, const int* in_sizes, int n_in,
                              void* d_out, int out_size) {
    const float* x      = (const float*)d_in[0];
    const float* Wq     = (const float*)d_in[2];
    const float* bq     = (const float*)d_in[3];
    const float* Wk     = (const float*)d_in[4];
    const float* bk     = (const float*)d_in[5];
    const float* Wv     = (const float*)d_in[6];
    const float* bv     = (const float*)d_in[7];
    const float* Wo     = (const float*)d_in[8];
    const float* bo     = (const float*)d_in[9];
    const float* scalar = (const float*)d_in[10];
    float* out = (float*)d_out;

    __half *xh, *wh, *woph, *ah, *qh, *kh, *vh;
    float *bqkv;
    cudaGetSymbolAddress((void**)&xh,   g_xh);
    cudaGetSymbolAddress((void**)&wh,   g_wh);
    cudaGetSymbolAddress((void**)&woph, g_woph);
    cudaGetSymbolAddress((void**)&ah,   g_ah);
    cudaGetSymbolAddress((void**)&qh,   g_qh);
    cudaGetSymbolAddress((void**)&kh,   g_kh);
    cudaGetSymbolAddress((void**)&vh,   g_vh);
    cudaGetSymbolAddress((void**)&bqkv, g_bqkv);

    cudaFuncSetAttribute(gemm_h, cudaFuncAttributeMaxDynamicSharedMemorySize, GSMEM);

    // fused prep: x->f16, pack W, permute Wo, pack biases
    prep_all<<<20492, 256>>>(x, Wq, Wk, Wv, bq, bk, bv, Wo);

    // fused QKV projection: N = 3072, f16 outputs
    gemm_h<<<dim3(3*DD/128, ROWS/128), 128, GSMEM>>>(
        xh, wh, bqkv, qh, kh, vh, 1);

    kv_partial<<<dim3(BH, KV_PARTS), 256>>>();
    kv_reduce<<<dim3(BH, 16), 256>>>();
    attn_qkv<<<dim3(LL / 64, HH, BB), 128>>>(scalar);

    // output projection: N = 1024, fp32 output
    gemm_h<<<dim3(DD/128, ROWS/128), 128, GSMEM>>>(
        ah, woph, bo, out, out, out, 0);
}

// round 12
// speedup vs baseline: 1.1079x; 1.0421x over previous
#include <cuda_runtime.h>
#include <cuda_fp16.h>
#include <stdint.h>

// ---------------- problem constants -----------------------------------------
#define LL 4096
#define BB 4
#define DD 1024
#define HH 16
#define HD 64
#define ROWS (LL*BB)          // 16384
#define BH   (BB*HH)          // 64
#define KV_PARTS 16
#define LPART (LL/KV_PARTS)   // 256

// ---------------- scratch (device globals; cudaMalloc is banned) ------------
__device__ __align__(256) __half g_xh  [(size_t)ROWS*DD];    // X in f16
__device__ __align__(256) __half g_wh  [(size_t)3*DD*DD];    // [Wq;Wk;Wv] f16
__device__ __align__(256) __half g_woph[(size_t)DD*DD];      // Wo permuted f16
__device__ __align__(256) float  g_bqkv[(size_t)3*DD];       // [bq;bk;bv]
__device__ __align__(256) __half g_qh  [(size_t)ROWS*DD];    // q (unscaled) f16
__device__ __align__(256) __half g_kh  [(size_t)ROWS*DD];
__device__ __align__(256) __half g_vh  [(size_t)ROWS*DD];
__device__ __align__(256) __half g_ah  [(size_t)ROWS*DD];    // attn out f16
__device__ __align__(256) float  g_kvp [(size_t)KV_PARTS*BH*HD*HD];
__device__ __align__(256) __half g_kvTh[(size_t)BH*HD*HD];   // reduced KV^T, f16

// ---------------- helpers -----------------------------------------------------
__device__ __forceinline__ uint32_t f2tf(float x) {
    uint32_t u; asm("cvt.rna.tf32.f32 %0, %1;" : "=r"(u) : "f"(x)); return u;
}
__device__ __forceinline__ uint32_t smem_u32(const void* p) {
    uint32_t a;
    asm("{ .reg .u64 t; cvta.to.shared.u64 t, %1; cvt.u32.u64 %0, t; }" : "=r"(a) : "l"(p));
    return a;
}
__device__ __forceinline__ void cp16(uint32_t saddr, const void* gaddr) {
    asm volatile("cp.async.cg.shared.global [%0], [%1], 16;" :: "r"(saddr), "l"(gaddr));
}
__device__ __forceinline__ void ldsm4(uint32_t* r, uint32_t a) {
    asm volatile("ldmatrix.sync.aligned.m8n8.x4.shared.b16 {%0,%1,%2,%3}, [%4];"
        : "=r"(r[0]), "=r"(r[1]), "=r"(r[2]), "=r"(r[3]) : "r"(a));
}
__device__ __forceinline__ void mma16(float c[4], const uint32_t a[4],
                                      uint32_t b0, uint32_t b1) {
    asm volatile(
        "mma.sync.aligned.m16n8k16.row.col.f32.f16.f16.f32 "
        "{%0,%1,%2,%3}, {%4,%5,%6,%7}, {%8,%9}, {%0,%1,%2,%3};"
        : "+f"(c[0]), "+f"(c[1]), "+f"(c[2]), "+f"(c[3])
        : "r"(a[0]), "r"(a[1]), "r"(a[2]), "r"(a[3]), "r"(b0), "r"(b1));
}
__device__ __forceinline__ void mma8(float c[4], const uint32_t a[4],
                                     uint32_t b0, uint32_t b1) {
    asm volatile(
        "mma.sync.aligned.m16n8k8.row.col.f32.tf32.tf32.f32 "
        "{%0,%1,%2,%3}, {%4,%5,%6,%7}, {%8,%9}, {%0,%1,%2,%3};"
        : "+f"(c[0]), "+f"(c[1]), "+f"(c[2]), "+f"(c[3])
        : "r"(a[0]), "r"(a[1]), "r"(a[2]), "r"(a[3]), "r"(b0), "r"(b1));
}

// =============================================================================
// Fused prep kernel: block-range dispatch
// =============================================================================
__global__ void prep_all(const float* __restrict__ X,
                         const float* __restrict__ Wq, const float* __restrict__ Wk,
                         const float* __restrict__ Wv,
                         const float* __restrict__ bq, const float* __restrict__ bk,
                         const float* __restrict__ bv,
                         const float* __restrict__ Wo) {
    const int blk = blockIdx.x;
    const int tid = threadIdx.x;
    if (blk < 16384) {
        size_t i = ((size_t)blk * 256 + tid) * 4;
        float4 v = *(const float4*)(X + i);
        *(__half2*)(g_xh + i)     = __floats2half2_rn(v.x, v.y);
        *(__half2*)(g_xh + i + 2) = __floats2half2_rn(v.z, v.w);
    } else if (blk < 19456) {
        int r = blk - 16384;                            // 0..3071
        const float* src = (r < 1024) ? Wq : (r < 2048) ? Wk : Wv;
        int lr = r & 1023;
        int c = tid * 4;
        float4 v = *(const float4*)(src + (size_t)lr * DD + c);
        *(__half2*)(g_wh + (size_t)r * DD + c)     = __floats2half2_rn(v.x, v.y);
        *(__half2*)(g_wh + (size_t)r * DD + c + 2) = __floats2half2_rn(v.z, v.w);
    } else if (blk < 20480) {
        __shared__ float srow[DD];
        const int j = blk - 19456;
#pragma unroll
        for (int i = 0; i < 4; ++i) srow[tid + 256*i] = Wo[(size_t)j*DD + tid + 256*i];
        __syncthreads();
#pragma unroll
        for (int i = 0; i < 4; ++i) {
            int f = tid + 256*i;                         // f = h*64 + t
            g_woph[(size_t)j*DD + f] = __float2half_rn(srow[((f & 63) << 4) | (f >> 6)]);
        }
    } else {
        int idx = (blk - 20480) * 256 + tid;             // 0..3071
        int t = idx >> 10;
        const float* src = (t == 0) ? bq : (t == 1) ? bk : bv;
        g_bqkv[idx] = src[idx & 1023];
    }
}

// =============================================================================
// FP16 tensor-core GEMM:  C = A @ B^T + bias   (frozen at R11)
// =============================================================================
#define STA  16384                 // A stage bytes (128 rows x 128B)
#define STS_ (2*STA)               // 32768
#define GSMEM (3 * STS_)           // 98304
#define NKT  16                    // 1024 / 64

__global__ void __launch_bounds__(128, 2) gemm_h(
    const __half* __restrict__ A, const __half* __restrict__ B,
    const float* __restrict__ bias,
    void* __restrict__ o0, void* __restrict__ o1, void* __restrict__ o2,
    int half_out)
{
    extern __shared__ char smem[];
    const uint32_t sb = smem_u32(smem);
    const int tid  = threadIdx.x;
    const int wid  = tid >> 5;
    const int lane = tid & 31;
    const int n0 = blockIdx.x * 128;
    const int m0 = blockIdx.y * 128;
    const int wm = (wid & 1) * 64;
    const int wn = (wid >> 1) * 64;

    const int row0 = tid >> 3, seg = tid & 7;
    const uint32_t sm_base = (uint32_t)(row0*128 + ((seg ^ (row0 & 7)) << 4));
    const char* Abase = (const char*)A + (size_t)m0 * 2048 + row0*2048 + seg*16;
    const char* Bbase = (const char*)B + (size_t)n0 * 2048 + row0*2048 + seg*16;

#define LOADC(c) do {                                                    \
        uint32_t ab_ = sb + ((c) % 3)*STS_ + sm_base;                    \
        uint32_t bb_ = ab_ + STA;                                        \
        const char* ga_ = Abase + (size_t)(c)*128;                       \
        const char* gb_ = Bbase + (size_t)(c)*128;                       \
        _Pragma("unroll") for (int i_ = 0; i_ < 8; ++i_) {               \
            cp16(ab_ + i_*2048, ga_ + i_*32768);                         \
            cp16(bb_ + i_*2048, gb_ + i_*32768);                         \
        }                                                                \
        asm volatile("cp.async.commit_group;" ::: "memory");             \
    } while (0)

    const int a_row = wm + (lane & 15);
    const int b_row = wn + (lane & 7) + ((lane >> 4) << 3);
    const int lo4   = (lane & 7) << 4;
    const int a_hi  = lane >> 4;
    const int b_hi  = (lane >> 3) & 1;

    float acc[4][8][4];
#pragma unroll
    for (int i = 0; i < 4; ++i)
#pragma unroll
        for (int j = 0; j < 8; ++j)
#pragma unroll
            for (int t = 0; t < 4; ++t) acc[i][j][t] = 0.f;

    LOADC(0);
    LOADC(1);

    for (int kt = 0; kt < NKT; ++kt) {
        if (kt + 1 < NKT) asm volatile("cp.async.wait_group 1;" ::: "memory");
        else              asm volatile("cp.async.wait_group 0;" ::: "memory");
        __syncthreads();

        const bool do_load = (kt + 2 < NKT);
        const uint32_t nab = sb + ((kt + 2) % 3)*STS_ + sm_base;
        const uint32_t nbb = nab + STA;
        const char* nga = Abase + (size_t)(kt + 2)*128;
        const char* ngb = Bbase + (size_t)(kt + 2)*128;

        const uint32_t sa = sb + (kt % 3) * STS_;
        const uint32_t aB = sa + a_row*128;
        const uint32_t bB = sa + STA + b_row*128;

#pragma unroll
        for (int s = 0; s < 4; ++s) {
            uint32_t af[4][4], bf[4][4];
            const uint32_t asg = (uint32_t)(((2*s + a_hi) << 4) ^ lo4);
            const uint32_t bsg = (uint32_t)(((2*s + b_hi) << 4) ^ lo4);
#pragma unroll
            for (int mt = 0; mt < 4; ++mt)
                ldsm4(af[mt], aB + mt*2048 + asg);
#pragma unroll
            for (int p = 0; p < 4; ++p)
                ldsm4(bf[p], bB + p*2048 + bsg);
            if (do_load) {
                cp16(nab + (2*s  )*2048, nga + (size_t)(2*s  )*32768);
                cp16(nab + (2*s+1)*2048, nga + (size_t)(2*s+1)*32768);
                cp16(nbb + (2*s  )*2048, ngb + (size_t)(2*s  )*32768);
                cp16(nbb + (2*s+1)*2048, ngb + (size_t)(2*s+1)*32768);
            }
#pragma unroll
            for (int mt = 0; mt < 4; ++mt)
#pragma unroll
                for (int nt = 0; nt < 8; ++nt)
                    mma16(acc[mt][nt], af[mt],
                          bf[nt >> 1][(nt & 1) * 2], bf[nt >> 1][(nt & 1) * 2 + 1]);
        }
        if (do_load)
            asm volatile("cp.async.commit_group;" ::: "memory");
    }

    if (half_out) {
        const int t = n0 >> 10;
        __half* outp = (t == 0) ? (__half*)o0 : (t == 1) ? (__half*)o1 : (__half*)o2;
#pragma unroll
        for (int mt = 0; mt < 4; ++mt) {
#pragma unroll
            for (int nt = 0; nt < 8; ++nt) {
                int row = m0 + wm + mt*16 + (lane >> 2);
                int gn  = n0 + wn + nt*8 + 2*(lane & 3);
                int col = gn & 1023;
                float b0 = bias[gn], b1 = bias[gn + 1];
                *(__half2*)&outp[(size_t)row * 1024 + col] =
                    __floats2half2_rn(acc[mt][nt][0] + b0, acc[mt][nt][1] + b1);
                *(__half2*)&outp[(size_t)(row + 8) * 1024 + col] =
                    __floats2half2_rn(acc[mt][nt][2] + b0, acc[mt][nt][3] + b1);
            }
        }
    } else {
        float* outp = (float*)o0;
#pragma unroll
        for (int mt = 0; mt < 4; ++mt) {
#pragma unroll
            for (int nt = 0; nt < 8; ++nt) {
                int row = m0 + wm + mt*16 + (lane >> 2);
                int gn  = n0 + wn + nt*8 + 2*(lane & 3);
                float b0 = bias[gn], b1 = bias[gn + 1];
                *(float2*)&outp[(size_t)row * 1024 + gn] =
                    make_float2(acc[mt][nt][0] + b0, acc[mt][nt][1] + b1);
                *(float2*)&outp[(size_t)(row + 8) * 1024 + gn] =
                    make_float2(acc[mt][nt][2] + b0, acc[mt][nt][3] + b1);
            }
        }
    }
}

// =============================================================================
// partial KV^T per (b,h): kvT[e][d] = sum_l v[l][e]*k[l][d]
// f16 in -> tf32 staging -> tf32 mma.  Double-buffered smem: ONE sync/iter.
// =============================================================================
#define SW(r, c) (((r) << 5) + ((c) ^ (((((r) + ((r) >> 3)) & 7)) << 2)))

__global__ void __launch_bounds__(256) kv_partial()
{
    const int bh = blockIdx.x, part = blockIdx.y;
    const int b = bh >> 4, h = bh & 15;

    __shared__ uint32_t vTs[2][64 * 32];
    __shared__ uint32_t kTs[2][64 * 32];

    const int tid  = threadIdx.x;
    const int lane = tid & 31;
    const int warp = tid >> 5;
    const int wm = (warp >> 1) * 16;
    const int wn = (warp & 1) * 32;

    float acc[4][4];
#pragma unroll
    for (int i = 0; i < 4; ++i)
#pragma unroll
        for (int t = 0; t < 4; ++t) acc[i][t] = 0.f;

    const int l_lo = tid >> 3;
    const int d8   = (tid & 7) * 8;
    const size_t colbase = (size_t)h * 64;

    for (int it = 0; it < LPART/32; ++it) {
        const int l0 = part * LPART + it * 32;
        const int bu = it & 1;
        size_t g = ((size_t)(l0 + l_lo) * BB + b) * DD + colbase + d8;
        uint4 rv = *(const uint4*)(g_vh + g);     // 8 halves
        uint4 rk = *(const uint4*)(g_kh + g);
        const __half2* hv = (const __half2*)&rv;
        const __half2* hk = (const __half2*)&rk;
#pragma unroll
        for (int j = 0; j < 4; ++j) {
            float2 fv = __half22float2(hv[j]);
            float2 fk = __half22float2(hk[j]);
            vTs[bu][SW(d8 + 2*j,     l_lo)] = f2tf(fv.x);
            vTs[bu][SW(d8 + 2*j + 1, l_lo)] = f2tf(fv.y);
            kTs[bu][SW(d8 + 2*j,     l_lo)] = f2tf(fk.x);
            kTs[bu][SW(d8 + 2*j + 1, l_lo)] = f2tf(fk.y);
        }
        __syncthreads();

#pragma unroll
        for (int kk = 0; kk < 32; kk += 8) {
            uint32_t af[4];
            int r = wm + (lane >> 2);
            int c = kk + (lane & 3);
            af[0] = vTs[bu][SW(r,     c)];
            af[1] = vTs[bu][SW(r + 8, c)];
            af[2] = vTs[bu][SW(r,     c + 4)];
            af[3] = vTs[bu][SW(r + 8, c + 4)];
#pragma unroll
            for (int nt = 0; nt < 4; ++nt) {
                int rn = wn + nt*8 + (lane >> 2);
                uint32_t b0 = kTs[bu][SW(rn, c)];
                uint32_t b1 = kTs[bu][SW(rn, c + 4)];
                mma8(acc[nt], af, b0, b1);
            }
        }
    }

    float* out = g_kvp + ((size_t)part * BH + bh) * 4096;
#pragma unroll
    for (int nt = 0; nt < 4; ++nt) {
        int e = wm + (lane >> 2);
        int d = wn + nt*8 + 2*(lane & 3);
        *(float2*)&out[(e    ) * 64 + d] = make_float2(acc[nt][0], acc[nt][1]);
        *(float2*)&out[(e + 8) * 64 + d] = make_float2(acc[nt][2], acc[nt][3]);
    }
}

// deterministic fixed-order reduce; grid (BH, 16); output f16
__global__ void kv_reduce() {
    const int bh = blockIdx.x;
    const int i  = blockIdx.y * 256 + threadIdx.x;      // 0..4095
    float s = 0.f;
#pragma unroll
    for (int p = 0; p < KV_PARTS; ++p)
        s += g_kvp[((size_t)p * BH + bh) * 4096 + i];
    g_kvTh[(size_t)bh * 4096 + i] = __float2half_rn(s);
}

// =============================================================================
// attn = (q @ kvT^T) * (0.125/scalar) per (b,h)
// f16 mma16 + cp.async + ldmatrix (fragment map cloned from gemm_h, mt=1).
// Math bit-identical to the tf32 version (f16 -> tf32 is exact).
// =============================================================================
__global__ void __launch_bounds__(128) attn_qkv(const float* __restrict__ scalar_ptr)
{
    const int lc = blockIdx.x;
    const int h  = blockIdx.y;
    const int b  = blockIdx.z;
    const int bh = b * 16 + h;
    const int l0 = lc * 64;

    __shared__ __half qs [64 * 64];   // 8KB, swizzled 128B rows
    __shared__ __half kvs[64 * 64];   // 8KB

    const uint32_t qsb = smem_u32(qs);
    const uint32_t kvb = smem_u32(kvs);

    const int tid  = threadIdx.x;
    const int lane = tid & 31;
    const int warp = tid >> 5;
    const int wm   = warp * 16;

    // cp.async loads: 512 slots per tile; slot s -> row s>>3, seg s&7
#pragma unroll
    for (int i = 0; i < 4; ++i) {
        int s   = tid + 128 * i;
        int row = s >> 3, seg = s & 7;
        uint32_t dst = (uint32_t)(row*128 + ((seg ^ (row & 7)) << 4));
        const __half* qg = g_qh + ((size_t)(l0 + row) * BB + b) * DD
                                + (size_t)h * 64 + seg * 8;
        const __half* kg = g_kvTh + (size_t)bh * 4096 + (size_t)s * 8;
        cp16(qsb + dst, qg);
        cp16(kvb + dst, kg);
    }
    asm volatile("cp.async.commit_group;" ::: "memory");
    asm volatile("cp.async.wait_group 0;" ::: "memory");
    __syncthreads();

    // fragment addressing (same invariants as gemm_h)
    const int a_row = wm + (lane & 15);
    const int b_row = (lane & 7) + ((lane >> 4) << 3);
    const int lo4   = (lane & 7) << 4;
    const int a_hi  = lane >> 4;
    const int b_hi  = (lane >> 3) & 1;
    const uint32_t aB = qsb + a_row*128;
    const uint32_t bB = kvb + b_row*128;

    float acc[8][4];
#pragma unroll
    for (int i = 0; i < 8; ++i)
#pragma unroll
        for (int t = 0; t < 4; ++t) acc[i][t] = 0.f;

#pragma unroll
    for (int s = 0; s < 4; ++s) {                 // four k16 steps over K=64
        uint32_t af[4], bf[4][4];
        const uint32_t asg = (uint32_t)(((2*s + a_hi) << 4) ^ lo4);
        const uint32_t bsg = (uint32_t)(((2*s + b_hi) << 4) ^ lo4);
        ldsm4(af, aB + asg);
#pragma unroll
        for (int p = 0; p < 4; ++p)
            ldsm4(bf[p], bB + p*2048 + bsg);
#pragma unroll
        for (int nt = 0; nt < 8; ++nt)
            mma16(acc[nt], af,
                  bf[nt >> 1][(nt & 1) * 2], bf[nt >> 1][(nt & 1) * 2 + 1]);
    }

    const float scale = 0.125f / (*scalar_ptr);
#pragma unroll
    for (int nt = 0; nt < 8; ++nt) {
        int l = l0 + wm + (lane >> 2);
        int e = nt*8 + 2*(lane & 3);
        size_t o0 = ((size_t)l * BB + b) * DD + (size_t)h * 64 + e;
        size_t o1 = ((size_t)(l + 8) * BB + b) * DD + (size_t)h * 64 + e;
        *(__half2*)&g_ah[o0] = __floats2half2_rn(acc[nt][0]*scale, acc[nt][1]*scale);
        *(__half2*)&g_ah[o1] = __floats2half2_rn(acc[nt][2]*scale, acc[nt][3]*scale);
    }
}

// =============================================================================
// launch
// =============================================================================
extern "C" void kernel_launch(void* const* d_in, const int* in_sizes, int n_in,
                              void* d_out, int out_size) {
    const float* x      = (const float*)d_in[0];
    const float* Wq     = (const float*)d_in[2];
    const float* bq     = (const float*)d_in[3];
    const float* Wk     = (const float*)d_in[4];
    const float* bk     = (const float*)d_in[5];
    const float* Wv     = (const float*)d_in[6];
    const float* bv     = (const float*)d_in[7];
    const float* Wo     = (const float*)d_in[8];
    const float* bo     = (const float*)d_in[9];
    const float* scalar = (const float*)d_in[10];
    float* out = (float*)d_out;

    __half *xh, *wh, *woph, *ah, *qh, *kh, *vh;
    float *bqkv;
    cudaGetSymbolAddress((void**)&xh,   g_xh);
    cudaGetSymbolAddress((void**)&wh,   g_wh);
    cudaGetSymbolAddress((void**)&woph, g_woph);
    cudaGetSymbolAddress((void**)&ah,   g_ah);
    cudaGetSymbolAddress((void**)&qh,   g_qh);
    cudaGetSymbolAddress((void**)&kh,   g_kh);
    cudaGetSymbolAddress((void**)&vh,   g_vh);
    cudaGetSymbolAddress((void**)&bqkv, g_bqkv);

    cudaFuncSetAttribute(gemm_h, cudaFuncAttributeMaxDynamicSharedMemorySize, GSMEM);

    // fused prep: x->f16, pack W, permute Wo, pack biases
    prep_all<<<20492, 256>>>(x, Wq, Wk, Wv, bq, bk, bv, Wo);

    // fused QKV projection: N = 3072, f16 outputs
    gemm_h<<<dim3(3*DD/128, ROWS/128), 128, GSMEM>>>(
        xh, wh, bqkv, qh, kh, vh, 1);

    kv_partial<<<dim3(BH, KV_PARTS), 256>>>();
    kv_reduce<<<dim3(BH, 16), 256>>>();
    attn_qkv<<<dim3(LL / 64, HH, BB), 128>>>(scalar);

    // output projection: N = 1024, fp32 output
    gemm_h<<<dim3(DD/128, ROWS/128), 128, GSMEM>>>(
        ah, woph, bo, out, out, out, 0);
}

// round 13
// speedup vs baseline: 1.1988x; 1.0820x over previous
#include <cuda_runtime.h>
#include <cuda_fp16.h>
#include <stdint.h>

// ---------------- problem constants -----------------------------------------
#define LL 4096
#define BB 4
#define DD 1024
#define HH 16
#define HD 64
#define ROWS (LL*BB)          // 16384
#define BH   (BB*HH)          // 64
#define KV_PARTS 16
#define LPART (LL/KV_PARTS)   // 256

// ---------------- scratch (device globals; cudaMalloc is banned) ------------
__device__ __align__(256) __half g_xh  [(size_t)ROWS*DD];    // X in f16
__device__ __align__(256) __half g_wh  [(size_t)3*DD*DD];    // [Wq;Wk;Wv] f16
__device__ __align__(256) __half g_woph[(size_t)DD*DD];      // Wo permuted f16
__device__ __align__(256) float  g_bqkv[(size_t)3*DD];       // [bq;bk;bv]
__device__ __align__(256) __half g_qh  [(size_t)ROWS*DD];    // q (unscaled) f16
__device__ __align__(256) __half g_kh  [(size_t)ROWS*DD];
__device__ __align__(256) __half g_vh  [(size_t)ROWS*DD];
__device__ __align__(256) __half g_ah  [(size_t)ROWS*DD];    // attn out f16
__device__ __align__(256) float  g_kvp [(size_t)KV_PARTS*BH*HD*HD];
__device__ __align__(256) __half g_kvTh[(size_t)BH*HD*HD];   // reduced KV^T, f16

// ---------------- helpers -----------------------------------------------------
__device__ __forceinline__ uint32_t smem_u32(const void* p) {
    uint32_t a;
    asm("{ .reg .u64 t; cvta.to.shared.u64 t, %1; cvt.u32.u64 %0, t; }" : "=r"(a) : "l"(p));
    return a;
}
__device__ __forceinline__ void cp16(uint32_t saddr, const void* gaddr) {
    asm volatile("cp.async.cg.shared.global [%0], [%1], 16;" :: "r"(saddr), "l"(gaddr));
}
__device__ __forceinline__ void ldsm4(uint32_t* r, uint32_t a) {
    asm volatile("ldmatrix.sync.aligned.m8n8.x4.shared.b16 {%0,%1,%2,%3}, [%4];"
        : "=r"(r[0]), "=r"(r[1]), "=r"(r[2]), "=r"(r[3]) : "r"(a));
}
__device__ __forceinline__ void ldsm4t(uint32_t* r, uint32_t a) {
    asm volatile("ldmatrix.sync.aligned.m8n8.x4.trans.shared.b16 {%0,%1,%2,%3}, [%4];"
        : "=r"(r[0]), "=r"(r[1]), "=r"(r[2]), "=r"(r[3]) : "r"(a));
}
__device__ __forceinline__ void mma16(float c[4], const uint32_t a[4],
                                      uint32_t b0, uint32_t b1) {
    asm volatile(
        "mma.sync.aligned.m16n8k16.row.col.f32.f16.f16.f32 "
        "{%0,%1,%2,%3}, {%4,%5,%6,%7}, {%8,%9}, {%0,%1,%2,%3};"
        : "+f"(c[0]), "+f"(c[1]), "+f"(c[2]), "+f"(c[3])
        : "r"(a[0]), "r"(a[1]), "r"(a[2]), "r"(a[3]), "r"(b0), "r"(b1));
}

// =============================================================================
// Fused prep kernel: block-range dispatch
// =============================================================================
__global__ void prep_all(const float* __restrict__ X,
                         const float* __restrict__ Wq, const float* __restrict__ Wk,
                         const float* __restrict__ Wv,
                         const float* __restrict__ bq, const float* __restrict__ bk,
                         const float* __restrict__ bv,
                         const float* __restrict__ Wo) {
    const int blk = blockIdx.x;
    const int tid = threadIdx.x;
    if (blk < 16384) {
        size_t i = ((size_t)blk * 256 + tid) * 4;
        float4 v = *(const float4*)(X + i);
        *(__half2*)(g_xh + i)     = __floats2half2_rn(v.x, v.y);
        *(__half2*)(g_xh + i + 2) = __floats2half2_rn(v.z, v.w);
    } else if (blk < 19456) {
        int r = blk - 16384;                            // 0..3071
        const float* src = (r < 1024) ? Wq : (r < 2048) ? Wk : Wv;
        int lr = r & 1023;
        int c = tid * 4;
        float4 v = *(const float4*)(src + (size_t)lr * DD + c);
        *(__half2*)(g_wh + (size_t)r * DD + c)     = __floats2half2_rn(v.x, v.y);
        *(__half2*)(g_wh + (size_t)r * DD + c + 2) = __floats2half2_rn(v.z, v.w);
    } else if (blk < 20480) {
        __shared__ float srow[DD];
        const int j = blk - 19456;
#pragma unroll
        for (int i = 0; i < 4; ++i) srow[tid + 256*i] = Wo[(size_t)j*DD + tid + 256*i];
        __syncthreads();
#pragma unroll
        for (int i = 0; i < 4; ++i) {
            int f = tid + 256*i;                         // f = h*64 + t
            g_woph[(size_t)j*DD + f] = __float2half_rn(srow[((f & 63) << 4) | (f >> 6)]);
        }
    } else {
        int idx = (blk - 20480) * 256 + tid;             // 0..3071
        int t = idx >> 10;
        const float* src = (t == 0) ? bq : (t == 1) ? bk : bv;
        g_bqkv[idx] = src[idx & 1023];
    }
}

// =============================================================================
// FP16 tensor-core GEMM:  C = A @ B^T + bias   (frozen at R11)
// =============================================================================
#define STA  16384                 // A stage bytes (128 rows x 128B)
#define STS_ (2*STA)               // 32768
#define GSMEM (3 * STS_)           // 98304
#define NKT  16                    // 1024 / 64

__global__ void __launch_bounds__(128, 2) gemm_h(
    const __half* __restrict__ A, const __half* __restrict__ B,
    const float* __restrict__ bias,
    void* __restrict__ o0, void* __restrict__ o1, void* __restrict__ o2,
    int half_out)
{
    extern __shared__ char smem[];
    const uint32_t sb = smem_u32(smem);
    const int tid  = threadIdx.x;
    const int wid  = tid >> 5;
    const int lane = tid & 31;
    const int n0 = blockIdx.x * 128;
    const int m0 = blockIdx.y * 128;
    const int wm = (wid & 1) * 64;
    const int wn = (wid >> 1) * 64;

    const int row0 = tid >> 3, seg = tid & 7;
    const uint32_t sm_base = (uint32_t)(row0*128 + ((seg ^ (row0 & 7)) << 4));
    const char* Abase = (const char*)A + (size_t)m0 * 2048 + row0*2048 + seg*16;
    const char* Bbase = (const char*)B + (size_t)n0 * 2048 + row0*2048 + seg*16;

#define LOADC(c) do {                                                    \
        uint32_t ab_ = sb + ((c) % 3)*STS_ + sm_base;                    \
        uint32_t bb_ = ab_ + STA;                                        \
        const char* ga_ = Abase + (size_t)(c)*128;                       \
        const char* gb_ = Bbase + (size_t)(c)*128;                       \
        _Pragma("unroll") for (int i_ = 0; i_ < 8; ++i_) {               \
            cp16(ab_ + i_*2048, ga_ + i_*32768);                         \
            cp16(bb_ + i_*2048, gb_ + i_*32768);                         \
        }                                                                \
        asm volatile("cp.async.commit_group;" ::: "memory");             \
    } while (0)

    const int a_row = wm + (lane & 15);
    const int b_row = wn + (lane & 7) + ((lane >> 4) << 3);
    const int lo4   = (lane & 7) << 4;
    const int a_hi  = lane >> 4;
    const int b_hi  = (lane >> 3) & 1;

    float acc[4][8][4];
#pragma unroll
    for (int i = 0; i < 4; ++i)
#pragma unroll
        for (int j = 0; j < 8; ++j)
#pragma unroll
            for (int t = 0; t < 4; ++t) acc[i][j][t] = 0.f;

    LOADC(0);
    LOADC(1);

    for (int kt = 0; kt < NKT; ++kt) {
        if (kt + 1 < NKT) asm volatile("cp.async.wait_group 1;" ::: "memory");
        else              asm volatile("cp.async.wait_group 0;" ::: "memory");
        __syncthreads();

        const bool do_load = (kt + 2 < NKT);
        const uint32_t nab = sb + ((kt + 2) % 3)*STS_ + sm_base;
        const uint32_t nbb = nab + STA;
        const char* nga = Abase + (size_t)(kt + 2)*128;
        const char* ngb = Bbase + (size_t)(kt + 2)*128;

        const uint32_t sa = sb + (kt % 3) * STS_;
        const uint32_t aB = sa + a_row*128;
        const uint32_t bB = sa + STA + b_row*128;

#pragma unroll
        for (int s = 0; s < 4; ++s) {
            uint32_t af[4][4], bf[4][4];
            const uint32_t asg = (uint32_t)(((2*s + a_hi) << 4) ^ lo4);
            const uint32_t bsg = (uint32_t)(((2*s + b_hi) << 4) ^ lo4);
#pragma unroll
            for (int mt = 0; mt < 4; ++mt)
                ldsm4(af[mt], aB + mt*2048 + asg);
#pragma unroll
            for (int p = 0; p < 4; ++p)
                ldsm4(bf[p], bB + p*2048 + bsg);
            if (do_load) {
                cp16(nab + (2*s  )*2048, nga + (size_t)(2*s  )*32768);
                cp16(nab + (2*s+1)*2048, nga + (size_t)(2*s+1)*32768);
                cp16(nbb + (2*s  )*2048, ngb + (size_t)(2*s  )*32768);
                cp16(nbb + (2*s+1)*2048, ngb + (size_t)(2*s+1)*32768);
            }
#pragma unroll
            for (int mt = 0; mt < 4; ++mt)
#pragma unroll
                for (int nt = 0; nt < 8; ++nt)
                    mma16(acc[mt][nt], af[mt],
                          bf[nt >> 1][(nt & 1) * 2], bf[nt >> 1][(nt & 1) * 2 + 1]);
        }
        if (do_load)
            asm volatile("cp.async.commit_group;" ::: "memory");
    }

    if (half_out) {
        const int t = n0 >> 10;
        __half* outp = (t == 0) ? (__half*)o0 : (t == 1) ? (__half*)o1 : (__half*)o2;
#pragma unroll
        for (int mt = 0; mt < 4; ++mt) {
#pragma unroll
            for (int nt = 0; nt < 8; ++nt) {
                int row = m0 + wm + mt*16 + (lane >> 2);
                int gn  = n0 + wn + nt*8 + 2*(lane & 3);
                int col = gn & 1023;
                float b0 = bias[gn], b1 = bias[gn + 1];
                *(__half2*)&outp[(size_t)row * 1024 + col] =
                    __floats2half2_rn(acc[mt][nt][0] + b0, acc[mt][nt][1] + b1);
                *(__half2*)&outp[(size_t)(row + 8) * 1024 + col] =
                    __floats2half2_rn(acc[mt][nt][2] + b0, acc[mt][nt][3] + b1);
            }
        }
    } else {
        float* outp = (float*)o0;
#pragma unroll
        for (int mt = 0; mt < 4; ++mt) {
#pragma unroll
            for (int nt = 0; nt < 8; ++nt) {
                int row = m0 + wm + mt*16 + (lane >> 2);
                int gn  = n0 + wn + nt*8 + 2*(lane & 3);
                float b0 = bias[gn], b1 = bias[gn + 1];
                *(float2*)&outp[(size_t)row * 1024 + gn] =
                    make_float2(acc[mt][nt][0] + b0, acc[mt][nt][1] + b1);
                *(float2*)&outp[(size_t)(row + 8) * 1024 + gn] =
                    make_float2(acc[mt][nt][2] + b0, acc[mt][nt][3] + b1);
            }
        }
    }
}

// =============================================================================
// partial KV^T per (b,h): kvT[e][d] = sum_l v[l][e]*k[l][d]
// f16 mma16 with ldmatrix.trans; cp.async staging (3-stage ring, 1 sync/iter).
// 8 warps: e-tile (warp>>1)*16, d-tile (warp&1)*32.
// =============================================================================
#define KVCH (LPART/32)            // 8 chunks of 32 l-rows

__global__ void __launch_bounds__(256) kv_partial()
{
    const int bh = blockIdx.x, part = blockIdx.y;
    const int b = bh >> 4, h = bh & 15;

    // 3-stage ring: per stage 32 rows x 128B per tensor
    __shared__ __half vs[3][32*64];
    __shared__ __half ks[3][32*64];
    const uint32_t vsb = smem_u32(vs);
    const uint32_t ksb = smem_u32(ks);

    const int tid  = threadIdx.x;
    const int lane = tid & 31;
    const int warp = tid >> 5;
    const int e0 = (warp >> 1) * 16;
    const int d0 = (warp & 1) * 32;

    // staging: 256 slots (32 rows x 8 segs); thread t -> row t>>3, seg t&7
    const int srow = tid >> 3, sseg = tid & 7;
    const uint32_t sm_off = (uint32_t)(srow*128 + ((sseg ^ (srow & 7)) << 4));
    const size_t gbase = ((size_t)(part * LPART + srow) * BB + b) * DD
                       + (size_t)h * 64 + sseg * 8;

#define LOADKV(c) do {                                                   \
        size_t g_ = gbase + (size_t)(c) * 32 * BB * DD;                  \
        cp16(vsb + ((c) % 3) * 4096 + sm_off, g_vh + g_);                \
        cp16(ksb + ((c) % 3) * 4096 + sm_off, g_kh + g_);                \
        asm volatile("cp.async.commit_group;" ::: "memory");             \
    } while (0)

    // ldmatrix.trans addressing
    //  A (v): tile order (e0-7,l0-7)(e8-15,l0-7)(e0-7,l8-15)(e8-15,l8-15)
    //    lane -> row l += (lane&7) + ((lane>>4)<<3); col bytes = e0*2 + ((lane>>3)&1)*16
    //  B (k): tile order (d0-7,l0-7)(d0-7,l8-15)(d8-15,l0-7)(d8-15,l8-15)
    //    lane -> row l += (lane&7) + (((lane>>3)&1)<<3); col bytes = dcol + ((lane>>4)&1)*16
    const int a_lrow = (lane & 7) + ((lane >> 4) << 3);
    const int b_lrow = (lane & 7) + (((lane >> 3) & 1) << 3);
    const int a_cbyte = e0*2 + (((lane >> 3) & 1) << 4);   // 0..112, 16B units
    const int b_cbyte0 = d0*2 + (((lane >> 4) & 1) << 4);

    float acc[4][4];
#pragma unroll
    for (int i = 0; i < 4; ++i)
#pragma unroll
        for (int t = 0; t < 4; ++t) acc[i][t] = 0.f;

    LOADKV(0);
    LOADKV(1);

    for (int it = 0; it < KVCH; ++it) {
        if (it + 1 < KVCH) asm volatile("cp.async.wait_group 1;" ::: "memory");
        else               asm volatile("cp.async.wait_group 0;" ::: "memory");
        __syncthreads();
        if (it + 2 < KVCH) LOADKV(it + 2);

        const uint32_t vB = vsb + (it % 3) * 4096;
        const uint32_t kB = ksb + (it % 3) * 4096;

#pragma unroll
        for (int s = 0; s < 2; ++s) {            // two k16 steps over 32 l
            uint32_t af[4], bf[2][4];
            {
                int r = 16*s + a_lrow;
                ldsm4t(af, vB + r*128 + (uint32_t)(((a_cbyte >> 4) ^ (r & 7)) << 4));
            }
#pragma unroll
            for (int p = 0; p < 2; ++p) {        // d sub-tiles 0,16
                int r = 16*s + b_lrow;
                int cb = b_cbyte0 + p*32;
                ldsm4t(bf[p], kB + r*128 + (uint32_t)(((cb >> 4) ^ (r & 7)) << 4));
            }
#pragma unroll
            for (int nt = 0; nt < 4; ++nt)
                mma16(acc[nt], af,
                      bf[nt >> 1][(nt & 1) * 2], bf[nt >> 1][(nt & 1) * 2 + 1]);
        }
        __syncthreads();  // protect stage reuse: stage (it+2)%3 loaded next iter top
    }

    float* out = g_kvp + ((size_t)part * BH + bh) * 4096;
#pragma unroll
    for (int nt = 0; nt < 4; ++nt) {
        int e = e0 + (lane >> 2);
        int d = d0 + nt*8 + 2*(lane & 3);
        *(float2*)&out[(e    ) * 64 + d] = make_float2(acc[nt][0], acc[nt][1]);
        *(float2*)&out[(e + 8) * 64 + d] = make_float2(acc[nt][2], acc[nt][3]);
    }
}

// deterministic fixed-order reduce; grid (BH, 16); output f16
__global__ void kv_reduce() {
    const int bh = blockIdx.x;
    const int i  = blockIdx.y * 256 + threadIdx.x;      // 0..4095
    float s = 0.f;
#pragma unroll
    for (int p = 0; p < KV_PARTS; ++p)
        s += g_kvp[((size_t)p * BH + bh) * 4096 + i];
    g_kvTh[(size_t)bh * 4096 + i] = __float2half_rn(s);
}

// =============================================================================
// attn = (q @ kvT^T) * (0.125/scalar) per (b,h)   (frozen at R12)
// =============================================================================
__global__ void __launch_bounds__(128) attn_qkv(const float* __restrict__ scalar_ptr)
{
    const int lc = blockIdx.x;
    const int h  = blockIdx.y;
    const int b  = blockIdx.z;
    const int bh = b * 16 + h;
    const int l0 = lc * 64;

    __shared__ __half qs [64 * 64];
    __shared__ __half kvs[64 * 64];

    const uint32_t qsb = smem_u32(qs);
    const uint32_t kvb = smem_u32(kvs);

    const int tid  = threadIdx.x;
    const int lane = tid & 31;
    const int warp = tid >> 5;
    const int wm   = warp * 16;

#pragma unroll
    for (int i = 0; i < 4; ++i) {
        int s   = tid + 128 * i;
        int row = s >> 3, seg = s & 7;
        uint32_t dst = (uint32_t)(row*128 + ((seg ^ (row & 7)) << 4));
        const __half* qg = g_qh + ((size_t)(l0 + row) * BB + b) * DD
                                + (size_t)h * 64 + seg * 8;
        const __half* kg = g_kvTh + (size_t)bh * 4096 + (size_t)s * 8;
        cp16(qsb + dst, qg);
        cp16(kvb + dst, kg);
    }
    asm volatile("cp.async.commit_group;" ::: "memory");
    asm volatile("cp.async.wait_group 0;" ::: "memory");
    __syncthreads();

    const int a_row = wm + (lane & 15);
    const int b_row = (lane & 7) + ((lane >> 4) << 3);
    const int lo4   = (lane & 7) << 4;
    const int a_hi  = lane >> 4;
    const int b_hi  = (lane >> 3) & 1;
    const uint32_t aB = qsb + a_row*128;
    const uint32_t bB = kvb + b_row*128;

    float acc[8][4];
#pragma unroll
    for (int i = 0; i < 8; ++i)
#pragma unroll
        for (int t = 0; t < 4; ++t) acc[i][t] = 0.f;

#pragma unroll
    for (int s = 0; s < 4; ++s) {
        uint32_t af[4], bf[4][4];
        const uint32_t asg = (uint32_t)(((2*s + a_hi) << 4) ^ lo4);
        const uint32_t bsg = (uint32_t)(((2*s + b_hi) << 4) ^ lo4);
        ldsm4(af, aB + asg);
#pragma unroll
        for (int p = 0; p < 4; ++p)
            ldsm4(bf[p], bB + p*2048 + bsg);
#pragma unroll
        for (int nt = 0; nt < 8; ++nt)
            mma16(acc[nt], af,
                  bf[nt >> 1][(nt & 1) * 2], bf[nt >> 1][(nt & 1) * 2 + 1]);
    }

    const float scale = 0.125f / (*scalar_ptr);
#pragma unroll
    for (int nt = 0; nt < 8; ++nt) {
        int l = l0 + wm + (lane >> 2);
        int e = nt*8 + 2*(lane & 3);
        size_t o0 = ((size_t)l * BB + b) * DD + (size_t)h * 64 + e;
        size_t o1 = ((size_t)(l + 8) * BB + b) * DD + (size_t)h * 64 + e;
        *(__half2*)&g_ah[o0] = __floats2half2_rn(acc[nt][0]*scale, acc[nt][1]*scale);
        *(__half2*)&g_ah[o1] = __floats2half2_rn(acc[nt][2]*scale, acc[nt][3]*scale);
    }
}

// =============================================================================
// launch
// =============================================================================
extern "C" void kernel_launch(void* const* d_in, const int* in_sizes, int n_in,
                              void* d_out, int out_size) {
    const float* x      = (const float*)d_in[0];
    const float* Wq     = (const float*)d_in[2];
    const float* bq     = (const float*)d_in[3];
    const float* Wk     = (const float*)d_in[4];
    const float* bk     = (const float*)d_in[5];
    const float* Wv     = (const float*)d_in[6];
    const float* bv     = (const float*)d_in[7];
    const float* Wo     = (const float*)d_in[8];
    const float* bo     = (const float*)d_in[9];
    const float* scalar = (const float*)d_in[10];
    float* out = (float*)d_out;

    __half *xh, *wh, *woph, *ah, *qh, *kh, *vh;
    float *bqkv;
    cudaGetSymbolAddress((void**)&xh,   g_xh);
    cudaGetSymbolAddress((void**)&wh,   g_wh);
    cudaGetSymbolAddress((void**)&woph, g_woph);
    cudaGetSymbolAddress((void**)&ah,   g_ah);
    cudaGetSymbolAddress((void**)&qh,   g_qh);
    cudaGetSymbolAddress((void**)&kh,   g_kh);
    cudaGetSymbolAddress((void**)&vh,   g_vh);
    cudaGetSymbolAddress((void**)&bqkv, g_bqkv);

    cudaFuncSetAttribute(gemm_h, cudaFuncAttributeMaxDynamicSharedMemorySize, GSMEM);

    // fused prep: x->f16, pack W, permute Wo, pack biases
    prep_all<<<20492, 256>>>(x, Wq, Wk, Wv, bq, bk, bv, Wo);

    // fused QKV projection: N = 3072, f16 outputs
    gemm_h<<<dim3(3*DD/128, ROWS/128), 128, GSMEM>>>(
        xh, wh, bqkv, qh, kh, vh, 1);

    kv_partial<<<dim3(BH, KV_PARTS), 256>>>();
    kv_reduce<<<dim3(BH, 16), 256>>>();
    attn_qkv<<<dim3(LL / 64, HH, BB), 128>>>(scalar);

    // output projection: N = 1024, fp32 output
    gemm_h<<<dim3(DD/128, ROWS/128), 128, GSMEM>>>(
        ah, woph, bo, out, out, out, 0);
}

// round 14
// speedup vs baseline: 1.2057x; 1.0058x over previous
#include <cuda_runtime.h>
#include <cuda_fp16.h>
#include <stdint.h>

// ---------------- problem constants -----------------------------------------
#define LL 4096
#define BB 4
#define DD 1024
#define HH 16
#define HD 64
#define ROWS (LL*BB)          // 16384
#define BH   (BB*HH)          // 64
#define KV_PARTS 8
#define LPART (LL/KV_PARTS)   // 512

// ---------------- scratch (device globals; cudaMalloc is banned) ------------
__device__ __align__(256) __half g_xh  [(size_t)ROWS*DD];    // X in f16
__device__ __align__(256) __half g_wh  [(size_t)3*DD*DD];    // [Wq;Wk;Wv] f16
__device__ __align__(256) __half g_woph[(size_t)DD*DD];      // Wo permuted f16
__device__ __align__(256) float  g_bqkv[(size_t)3*DD];       // [bq;bk;bv]
__device__ __align__(256) __half g_qh  [(size_t)ROWS*DD];    // q (unscaled) f16
__device__ __align__(256) __half g_kh  [(size_t)ROWS*DD];
__device__ __align__(256) __half g_vh  [(size_t)ROWS*DD];
__device__ __align__(256) __half g_ah  [(size_t)ROWS*DD];    // attn out f16
__device__ __align__(256) float  g_kvp [(size_t)KV_PARTS*BH*HD*HD];
__device__ __align__(256) __half g_kvTh[(size_t)BH*HD*HD];   // reduced KV^T, f16

// ---------------- helpers -----------------------------------------------------
__device__ __forceinline__ uint32_t smem_u32(const void* p) {
    uint32_t a;
    asm("{ .reg .u64 t; cvta.to.shared.u64 t, %1; cvt.u32.u64 %0, t; }" : "=r"(a) : "l"(p));
    return a;
}
__device__ __forceinline__ void cp16(uint32_t saddr, const void* gaddr) {
    asm volatile("cp.async.cg.shared.global [%0], [%1], 16;" :: "r"(saddr), "l"(gaddr));
}
__device__ __forceinline__ void ldsm4(uint32_t* r, uint32_t a) {
    asm volatile("ldmatrix.sync.aligned.m8n8.x4.shared.b16 {%0,%1,%2,%3}, [%4];"
        : "=r"(r[0]), "=r"(r[1]), "=r"(r[2]), "=r"(r[3]) : "r"(a));
}
__device__ __forceinline__ void ldsm4t(uint32_t* r, uint32_t a) {
    asm volatile("ldmatrix.sync.aligned.m8n8.x4.trans.shared.b16 {%0,%1,%2,%3}, [%4];"
        : "=r"(r[0]), "=r"(r[1]), "=r"(r[2]), "=r"(r[3]) : "r"(a));
}
__device__ __forceinline__ void mma16(float c[4], const uint32_t a[4],
                                      uint32_t b0, uint32_t b1) {
    asm volatile(
        "mma.sync.aligned.m16n8k16.row.col.f32.f16.f16.f32 "
        "{%0,%1,%2,%3}, {%4,%5,%6,%7}, {%8,%9}, {%0,%1,%2,%3};"
        : "+f"(c[0]), "+f"(c[1]), "+f"(c[2]), "+f"(c[3])
        : "r"(a[0]), "r"(a[1]), "r"(a[2]), "r"(a[3]), "r"(b0), "r"(b1));
}

// =============================================================================
// Fused prep kernel: block-range dispatch
// =============================================================================
__global__ void prep_all(const float* __restrict__ X,
                         const float* __restrict__ Wq, const float* __restrict__ Wk,
                         const float* __restrict__ Wv,
                         const float* __restrict__ bq, const float* __restrict__ bk,
                         const float* __restrict__ bv,
                         const float* __restrict__ Wo) {
    const int blk = blockIdx.x;
    const int tid = threadIdx.x;
    if (blk < 16384) {
        size_t i = ((size_t)blk * 256 + tid) * 4;
        float4 v = *(const float4*)(X + i);
        *(__half2*)(g_xh + i)     = __floats2half2_rn(v.x, v.y);
        *(__half2*)(g_xh + i + 2) = __floats2half2_rn(v.z, v.w);
    } else if (blk < 19456) {
        int r = blk - 16384;                            // 0..3071
        const float* src = (r < 1024) ? Wq : (r < 2048) ? Wk : Wv;
        int lr = r & 1023;
        int c = tid * 4;
        float4 v = *(const float4*)(src + (size_t)lr * DD + c);
        *(__half2*)(g_wh + (size_t)r * DD + c)     = __floats2half2_rn(v.x, v.y);
        *(__half2*)(g_wh + (size_t)r * DD + c + 2) = __floats2half2_rn(v.z, v.w);
    } else if (blk < 20480) {
        __shared__ float srow[DD];
        const int j = blk - 19456;
#pragma unroll
        for (int i = 0; i < 4; ++i) srow[tid + 256*i] = Wo[(size_t)j*DD + tid + 256*i];
        __syncthreads();
#pragma unroll
        for (int i = 0; i < 4; ++i) {
            int f = tid + 256*i;                         // f = h*64 + t
            g_woph[(size_t)j*DD + f] = __float2half_rn(srow[((f & 63) << 4) | (f >> 6)]);
        }
    } else {
        int idx = (blk - 20480) * 256 + tid;             // 0..3071
        int t = idx >> 10;
        const float* src = (t == 0) ? bq : (t == 1) ? bk : bv;
        g_bqkv[idx] = src[idx & 1023];
    }
}

// =============================================================================
// FP16 tensor-core GEMM:  C = A @ B^T + bias   (frozen at R11)
// =============================================================================
#define STA  16384                 // A stage bytes (128 rows x 128B)
#define STS_ (2*STA)               // 32768
#define GSMEM (3 * STS_)           // 98304
#define NKT  16                    // 1024 / 64

__global__ void __launch_bounds__(128, 2) gemm_h(
    const __half* __restrict__ A, const __half* __restrict__ B,
    const float* __restrict__ bias,
    void* __restrict__ o0, void* __restrict__ o1, void* __restrict__ o2,
    int half_out)
{
    extern __shared__ char smem[];
    const uint32_t sb = smem_u32(smem);
    const int tid  = threadIdx.x;
    const int wid  = tid >> 5;
    const int lane = tid & 31;
    const int n0 = blockIdx.x * 128;
    const int m0 = blockIdx.y * 128;
    const int wm = (wid & 1) * 64;
    const int wn = (wid >> 1) * 64;

    const int row0 = tid >> 3, seg = tid & 7;
    const uint32_t sm_base = (uint32_t)(row0*128 + ((seg ^ (row0 & 7)) << 4));
    const char* Abase = (const char*)A + (size_t)m0 * 2048 + row0*2048 + seg*16;
    const char* Bbase = (const char*)B + (size_t)n0 * 2048 + row0*2048 + seg*16;

#define LOADC(c) do {                                                    \
        uint32_t ab_ = sb + ((c) % 3)*STS_ + sm_base;                    \
        uint32_t bb_ = ab_ + STA;                                        \
        const char* ga_ = Abase + (size_t)(c)*128;                       \
        const char* gb_ = Bbase + (size_t)(c)*128;                       \
        _Pragma("unroll") for (int i_ = 0; i_ < 8; ++i_) {               \
            cp16(ab_ + i_*2048, ga_ + i_*32768);                         \
            cp16(bb_ + i_*2048, gb_ + i_*32768);                         \
        }                                                                \
        asm volatile("cp.async.commit_group;" ::: "memory");             \
    } while (0)

    const int a_row = wm + (lane & 15);
    const int b_row = wn + (lane & 7) + ((lane >> 4) << 3);
    const int lo4   = (lane & 7) << 4;
    const int a_hi  = lane >> 4;
    const int b_hi  = (lane >> 3) & 1;

    float acc[4][8][4];
#pragma unroll
    for (int i = 0; i < 4; ++i)
#pragma unroll
        for (int j = 0; j < 8; ++j)
#pragma unroll
            for (int t = 0; t < 4; ++t) acc[i][j][t] = 0.f;

    LOADC(0);
    LOADC(1);

    for (int kt = 0; kt < NKT; ++kt) {
        if (kt + 1 < NKT) asm volatile("cp.async.wait_group 1;" ::: "memory");
        else              asm volatile("cp.async.wait_group 0;" ::: "memory");
        __syncthreads();

        const bool do_load = (kt + 2 < NKT);
        const uint32_t nab = sb + ((kt + 2) % 3)*STS_ + sm_base;
        const uint32_t nbb = nab + STA;
        const char* nga = Abase + (size_t)(kt + 2)*128;
        const char* ngb = Bbase + (size_t)(kt + 2)*128;

        const uint32_t sa = sb + (kt % 3) * STS_;
        const uint32_t aB = sa + a_row*128;
        const uint32_t bB = sa + STA + b_row*128;

#pragma unroll
        for (int s = 0; s < 4; ++s) {
            uint32_t af[4][4], bf[4][4];
            const uint32_t asg = (uint32_t)(((2*s + a_hi) << 4) ^ lo4);
            const uint32_t bsg = (uint32_t)(((2*s + b_hi) << 4) ^ lo4);
#pragma unroll
            for (int mt = 0; mt < 4; ++mt)
                ldsm4(af[mt], aB + mt*2048 + asg);
#pragma unroll
            for (int p = 0; p < 4; ++p)
                ldsm4(bf[p], bB + p*2048 + bsg);
            if (do_load) {
                cp16(nab + (2*s  )*2048, nga + (size_t)(2*s  )*32768);
                cp16(nab + (2*s+1)*2048, nga + (size_t)(2*s+1)*32768);
                cp16(nbb + (2*s  )*2048, ngb + (size_t)(2*s  )*32768);
                cp16(nbb + (2*s+1)*2048, ngb + (size_t)(2*s+1)*32768);
            }
#pragma unroll
            for (int mt = 0; mt < 4; ++mt)
#pragma unroll
                for (int nt = 0; nt < 8; ++nt)
                    mma16(acc[mt][nt], af[mt],
                          bf[nt >> 1][(nt & 1) * 2], bf[nt >> 1][(nt & 1) * 2 + 1]);
        }
        if (do_load)
            asm volatile("cp.async.commit_group;" ::: "memory");
    }

    if (half_out) {
        const int t = n0 >> 10;
        __half* outp = (t == 0) ? (__half*)o0 : (t == 1) ? (__half*)o1 : (__half*)o2;
#pragma unroll
        for (int mt = 0; mt < 4; ++mt) {
#pragma unroll
            for (int nt = 0; nt < 8; ++nt) {
                int row = m0 + wm + mt*16 + (lane >> 2);
                int gn  = n0 + wn + nt*8 + 2*(lane & 3);
                int col = gn & 1023;
                float b0 = bias[gn], b1 = bias[gn + 1];
                *(__half2*)&outp[(size_t)row * 1024 + col] =
                    __floats2half2_rn(acc[mt][nt][0] + b0, acc[mt][nt][1] + b1);
                *(__half2*)&outp[(size_t)(row + 8) * 1024 + col] =
                    __floats2half2_rn(acc[mt][nt][2] + b0, acc[mt][nt][3] + b1);
            }
        }
    } else {
        float* outp = (float*)o0;
#pragma unroll
        for (int mt = 0; mt < 4; ++mt) {
#pragma unroll
            for (int nt = 0; nt < 8; ++nt) {
                int row = m0 + wm + mt*16 + (lane >> 2);
                int gn  = n0 + wn + nt*8 + 2*(lane & 3);
                float b0 = bias[gn], b1 = bias[gn + 1];
                *(float2*)&outp[(size_t)row * 1024 + gn] =
                    make_float2(acc[mt][nt][0] + b0, acc[mt][nt][1] + b1);
                *(float2*)&outp[(size_t)(row + 8) * 1024 + gn] =
                    make_float2(acc[mt][nt][2] + b0, acc[mt][nt][3] + b1);
            }
        }
    }
}

// =============================================================================
// partial KV^T per (b,h): kvT[e][d] = sum_l v[l][e]*k[l][d]
// f16 mma16 with ldmatrix.trans; cp.async staging (3-stage ring, 1 sync/iter).
// =============================================================================
#define KVCH (LPART/32)            // 16 chunks of 32 l-rows

__global__ void __launch_bounds__(256) kv_partial()
{
    const int bh = blockIdx.x, part = blockIdx.y;
    const int b = bh >> 4, h = bh & 15;

    __shared__ __half vs[3][32*64];
    __shared__ __half ks[3][32*64];
    const uint32_t vsb = smem_u32(vs);
    const uint32_t ksb = smem_u32(ks);

    const int tid  = threadIdx.x;
    const int lane = tid & 31;
    const int warp = tid >> 5;
    const int e0 = (warp >> 1) * 16;
    const int d0 = (warp & 1) * 32;

    const int srow = tid >> 3, sseg = tid & 7;
    const uint32_t sm_off = (uint32_t)(srow*128 + ((sseg ^ (srow & 7)) << 4));
    const size_t gbase = ((size_t)(part * LPART + srow) * BB + b) * DD
                       + (size_t)h * 64 + sseg * 8;

#define LOADKV(c) do {                                                   \
        size_t g_ = gbase + (size_t)(c) * 32 * BB * DD;                  \
        cp16(vsb + ((c) % 3) * 4096 + sm_off, g_vh + g_);                \
        cp16(ksb + ((c) % 3) * 4096 + sm_off, g_kh + g_);                \
        asm volatile("cp.async.commit_group;" ::: "memory");             \
    } while (0)

    const int a_lrow = (lane & 7) + ((lane >> 4) << 3);
    const int b_lrow = (lane & 7) + (((lane >> 3) & 1) << 3);
    const int a_cbyte = e0*2 + (((lane >> 3) & 1) << 4);
    const int b_cbyte0 = d0*2 + (((lane >> 4) & 1) << 4);

    float acc[4][4];
#pragma unroll
    for (int i = 0; i < 4; ++i)
#pragma unroll
        for (int t = 0; t < 4; ++t) acc[i][t] = 0.f;

    LOADKV(0);
    LOADKV(1);

    for (int it = 0; it < KVCH; ++it) {
        if (it + 1 < KVCH) asm volatile("cp.async.wait_group 1;" ::: "memory");
        else               asm volatile("cp.async.wait_group 0;" ::: "memory");
        __syncthreads();
        if (it + 2 < KVCH) LOADKV(it + 2);

        const uint32_t vB = vsb + (it % 3) * 4096;
        const uint32_t kB = ksb + (it % 3) * 4096;

#pragma unroll
        for (int s = 0; s < 2; ++s) {
            uint32_t af[4], bf[2][4];
            {
                int r = 16*s + a_lrow;
                ldsm4t(af, vB + r*128 + (uint32_t)(((a_cbyte >> 4) ^ (r & 7)) << 4));
            }
#pragma unroll
            for (int p = 0; p < 2; ++p) {
                int r = 16*s + b_lrow;
                int cb = b_cbyte0 + p*32;
                ldsm4t(bf[p], kB + r*128 + (uint32_t)(((cb >> 4) ^ (r & 7)) << 4));
            }
#pragma unroll
            for (int nt = 0; nt < 4; ++nt)
                mma16(acc[nt], af,
                      bf[nt >> 1][(nt & 1) * 2], bf[nt >> 1][(nt & 1) * 2 + 1]);
        }
        __syncthreads();
    }

    float* out = g_kvp + ((size_t)part * BH + bh) * 4096;
#pragma unroll
    for (int nt = 0; nt < 4; ++nt) {
        int e = e0 + (lane >> 2);
        int d = d0 + nt*8 + 2*(lane & 3);
        *(float2*)&out[(e    ) * 64 + d] = make_float2(acc[nt][0], acc[nt][1]);
        *(float2*)&out[(e + 8) * 64 + d] = make_float2(acc[nt][2], acc[nt][3]);
    }
}

// deterministic fixed-order reduce; grid (BH, 16); output f16
__global__ void kv_reduce() {
    const int bh = blockIdx.x;
    const int i  = blockIdx.y * 256 + threadIdx.x;      // 0..4095
    float s = 0.f;
#pragma unroll
    for (int p = 0; p < KV_PARTS; ++p)
        s += g_kvp[((size_t)p * BH + bh) * 4096 + i];
    g_kvTh[(size_t)bh * 4096 + i] = __float2half_rn(s);
}

// =============================================================================
// attn = (q @ kvT^T) * (0.125/scalar) per (b,h)   (frozen at R12)
// =============================================================================
__global__ void __launch_bounds__(128) attn_qkv(const float* __restrict__ scalar_ptr)
{
    const int lc = blockIdx.x;
    const int h  = blockIdx.y;
    const int b  = blockIdx.z;
    const int bh = b * 16 + h;
    const int l0 = lc * 64;

    __shared__ __half qs [64 * 64];
    __shared__ __half kvs[64 * 64];

    const uint32_t qsb = smem_u32(qs);
    const uint32_t kvb = smem_u32(kvs);

    const int tid  = threadIdx.x;
    const int lane = tid & 31;
    const int warp = tid >> 5;
    const int wm   = warp * 16;

#pragma unroll
    for (int i = 0; i < 4; ++i) {
        int s   = tid + 128 * i;
        int row = s >> 3, seg = s & 7;
        uint32_t dst = (uint32_t)(row*128 + ((seg ^ (row & 7)) << 4));
        const __half* qg = g_qh + ((size_t)(l0 + row) * BB + b) * DD
                                + (size_t)h * 64 + seg * 8;
        const __half* kg = g_kvTh + (size_t)bh * 4096 + (size_t)s * 8;
        cp16(qsb + dst, qg);
        cp16(kvb + dst, kg);
    }
    asm volatile("cp.async.commit_group;" ::: "memory");
    asm volatile("cp.async.wait_group 0;" ::: "memory");
    __syncthreads();

    const int a_row = wm + (lane & 15);
    const int b_row = (lane & 7) + ((lane >> 4) << 3);
    const int lo4   = (lane & 7) << 4;
    const int a_hi  = lane >> 4;
    const int b_hi  = (lane >> 3) & 1;
    const uint32_t aB = qsb + a_row*128;
    const uint32_t bB = kvb + b_row*128;

    float acc[8][4];
#pragma unroll
    for (int i = 0; i < 8; ++i)
#pragma unroll
        for (int t = 0; t < 4; ++t) acc[i][t] = 0.f;

#pragma unroll
    for (int s = 0; s < 4; ++s) {
        uint32_t af[4], bf[4][4];
        const uint32_t asg = (uint32_t)(((2*s + a_hi) << 4) ^ lo4);
        const uint32_t bsg = (uint32_t)(((2*s + b_hi) << 4) ^ lo4);
        ldsm4(af, aB + asg);
#pragma unroll
        for (int p = 0; p < 4; ++p)
            ldsm4(bf[p], bB + p*2048 + bsg);
#pragma unroll
        for (int nt = 0; nt < 8; ++nt)
            mma16(acc[nt], af,
                  bf[nt >> 1][(nt & 1) * 2], bf[nt >> 1][(nt & 1) * 2 + 1]);
    }

    const float scale = 0.125f / (*scalar_ptr);
#pragma unroll
    for (int nt = 0; nt < 8; ++nt) {
        int l = l0 + wm + (lane >> 2);
        int e = nt*8 + 2*(lane & 3);
        size_t o0 = ((size_t)l * BB + b) * DD + (size_t)h * 64 + e;
        size_t o1 = ((size_t)(l + 8) * BB + b) * DD + (size_t)h * 64 + e;
        *(__half2*)&g_ah[o0] = __floats2half2_rn(acc[nt][0]*scale, acc[nt][1]*scale);
        *(__half2*)&g_ah[o1] = __floats2half2_rn(acc[nt][2]*scale, acc[nt][3]*scale);
    }
}

// =============================================================================
// launch: kv-proj first, then q-proj || (kv_partial -> kv_reduce) via stream
// fork/join (capture-legal event pattern), then attn, out-proj.
// =============================================================================
extern "C" void kernel_launch(void* const* d_in, const int* in_sizes, int n_in,
                              void* d_out, int out_size) {
    const float* x      = (const float*)d_in[0];
    const float* Wq     = (const float*)d_in[2];
    const float* bq     = (const float*)d_in[3];
    const float* Wk     = (const float*)d_in[4];
    const float* bk     = (const float*)d_in[5];
    const float* Wv     = (const float*)d_in[6];
    const float* bv     = (const float*)d_in[7];
    const float* Wo     = (const float*)d_in[8];
    const float* bo     = (const float*)d_in[9];
    const float* scalar = (const float*)d_in[10];
    float* out = (float*)d_out;

    __half *xh, *wh, *woph, *ah, *qh, *kh, *vh;
    float *bqkv;
    cudaGetSymbolAddress((void**)&xh,   g_xh);
    cudaGetSymbolAddress((void**)&wh,   g_wh);
    cudaGetSymbolAddress((void**)&woph, g_woph);
    cudaGetSymbolAddress((void**)&ah,   g_ah);
    cudaGetSymbolAddress((void**)&qh,   g_qh);
    cudaGetSymbolAddress((void**)&kh,   g_kh);
    cudaGetSymbolAddress((void**)&vh,   g_vh);
    cudaGetSymbolAddress((void**)&bqkv, g_bqkv);

    static cudaStream_t s2 = nullptr;
    static cudaEvent_t ev1 = nullptr, ev2 = nullptr;
    if (!s2) {
        cudaStreamCreateWithFlags(&s2, cudaStreamNonBlocking);
        cudaEventCreateWithFlags(&ev1, cudaEventDisableTiming);
        cudaEventCreateWithFlags(&ev2, cudaEventDisableTiming);
        cudaFuncSetAttribute(gemm_h, cudaFuncAttributeMaxDynamicSharedMemorySize,
                             GSMEM);
    }

    // fused prep: x->f16, pack W, permute Wo, pack biases
    prep_all<<<20492, 256>>>(x, Wq, Wk, Wv, bq, bk, bv, Wo);

    // k,v projection: N = 2048 (weights rows [1024, 3072) of g_wh)
    gemm_h<<<dim3(2*DD/128, ROWS/128), 128, GSMEM>>>(
        xh, wh + (size_t)DD*DD, bqkv + DD, kh, vh, vh, 1);

    // fork: kv chain on side stream, q projection on main stream (concurrent)
    cudaEventRecord(ev1, 0);
    cudaStreamWaitEvent(s2, ev1, 0);
    kv_partial<<<dim3(BH, KV_PARTS), 256, 0, s2>>>();
    kv_reduce<<<dim3(BH, 16), 256, 0, s2>>>();
    cudaEventRecord(ev2, s2);

    // q projection: N = 1024
    gemm_h<<<dim3(DD/128, ROWS/128), 128, GSMEM>>>(
        xh, wh, bqkv, qh, qh, qh, 1);

    // join
    cudaStreamWaitEvent(0, ev2, 0);

    attn_qkv<<<dim3(LL / 64, HH, BB), 128>>>(scalar);

    // output projection: N = 1024, fp32 output
    gemm_h<<<dim3(DD/128, ROWS/128), 128, GSMEM>>>(
        ah, woph, bo, out, out, out, 0);
}